// round 3
// baseline (speedup 1.0000x reference)
#include <cuda_runtime.h>
#include <cuda_bf16.h>
#include <math.h>

#define BB   128
#define CH   24
#define PIX  1024
#define D    (CH*PIX)
#define MM   5
#define EPSV 1e-5f
#define LAMV 1e-4f

#define RS   35                       // padded row stride (bank-conflict-free)
#define IN1  (24*34*RS)               // 28560 floats
#define WD1  (64*24*9*2)              // 27648 floats (duplicated pairs)
#define SMEM1 ((IN1 + WD1)*4)         // 224832 B

#define IN2C (32*34*RS)               // 38080 floats (one 32-ic chunk, full image)
#define WD2C (24*32*9*2)              // 13824 floats
#define SMEM2 ((IN2C + WD2C)*4)       // 207616 B

typedef unsigned long long u64;

__device__ __forceinline__ u64 pk2(float lo, float hi) {
    u64 r; asm("mov.b64 %0, {%1,%2};" : "=l"(r) : "f"(lo), "f"(hi)); return r;
}
__device__ __forceinline__ float2 upk2(u64 v) {
    float2 f; asm("mov.b64 {%0,%1}, %2;" : "=f"(f.x), "=f"(f.y) : "l"(v)); return f;
}
#define FMA2(acc, a, b) asm("fma.rn.f32x2 %0, %1, %2, %0;" : "+l"(acc) : "l"(a), "l"(b))

// ---------------- device scratch ----------------
__device__ float g_pre [BB*D];
__device__ float g_xp  [BB*D];
__device__ float g_X   [MM*BB*D];
__device__ float g_F   [MM*BB*D];
__device__ float g_t1  [BB*64*PIX];
__device__ float g_t2  [BB*D];
__device__ float g_al  [BB*MM];
__device__ float g_s1  [BB*16];        // gn1 per-(b,grp): mean, rstd
__device__ float g_s2  [BB*16];        // gn2 per-(b,grp): mean, rstd
__device__ float g_bmu [CH];
__device__ float g_brs [CH];
__device__ float g_pmu [CH];
__device__ float g_prs [CH];
__device__ float g_pool[BB*CH*16];

// ---------------- block reduce (sum, sumsq) ----------------
__device__ __forceinline__ void block_reduce_2(float& s, float& s2, float* shm) {
    __syncthreads();
    int lane = threadIdx.x & 31, wid = threadIdx.x >> 5;
#pragma unroll
    for (int o = 16; o > 0; o >>= 1) {
        s  += __shfl_down_sync(0xffffffffu, s,  o);
        s2 += __shfl_down_sync(0xffffffffu, s2, o);
    }
    if (lane == 0) { shm[wid] = s; shm[32 + wid] = s2; }
    __syncthreads();
    int nw = (blockDim.x + 31) >> 5;
    if (wid == 0) {
        s  = (lane < nw) ? shm[lane]      : 0.f;
        s2 = (lane < nw) ? shm[32 + lane] : 0.f;
#pragma unroll
        for (int o = 16; o > 0; o >>= 1) {
            s  += __shfl_down_sync(0xffffffffu, s,  o);
            s2 += __shfl_down_sync(0xffffffffu, s2, o);
        }
        if (lane == 0) { shm[0] = s; shm[32] = s2; }
    }
    __syncthreads();
    s = shm[0]; s2 = shm[32];
}

// ---------------- pre conv 3->24 (+bias) ----------------
__global__ void preconv_kernel(const float* __restrict__ x, const float* __restrict__ w,
                               const float* __restrict__ bias, float* __restrict__ out) {
    __shared__ float s[3*34*34];
    int b = blockIdx.x, tid = threadIdx.x;
    for (int i = tid; i < 3*1156; i += 256) {
        int c = i / 1156, rem = i % 1156, r = rem / 34, cx = rem % 34;
        float v = 0.f;
        if (r >= 1 && r <= 32 && cx >= 1 && cx <= 32)
            v = x[((b*3 + c)*32 + (r-1))*32 + (cx-1)];
        s[i] = v;
    }
    __syncthreads();
    int py = tid >> 3, px0 = (tid & 7) << 2;
    for (int oc0 = 0; oc0 < 24; oc0 += 8) {
        float acc[8][4];
#pragma unroll
        for (int j = 0; j < 8; j++) {
            float bv = __ldg(&bias[oc0 + j]);
#pragma unroll
            for (int p = 0; p < 4; p++) acc[j][p] = bv;
        }
        for (int ic = 0; ic < 3; ic++)
#pragma unroll
            for (int ky = 0; ky < 3; ky++) {
                const float* row = &s[ic*1156 + (py + ky)*34 + px0];
                float r0=row[0],r1=row[1],r2=row[2],r3=row[3],r4=row[4],r5=row[5];
#pragma unroll
                for (int j = 0; j < 8; j++) {
                    int oc = oc0 + j;
                    const float* wq = &w[((oc*3 + ic)*3 + ky)*3];
                    float w0=__ldg(wq), w1=__ldg(wq+1), w2=__ldg(wq+2);
                    acc[j][0] += r0*w0 + r1*w1 + r2*w2;
                    acc[j][1] += r1*w0 + r2*w1 + r3*w2;
                    acc[j][2] += r2*w0 + r3*w1 + r4*w2;
                    acc[j][3] += r3*w0 + r4*w1 + r5*w2;
                }
            }
#pragma unroll
        for (int j = 0; j < 8; j++)
#pragma unroll
            for (int p = 0; p < 4; p++)
                out[(b*24 + oc0 + j)*PIX + py*32 + px0 + p] = acc[j][p];
    }
}

// ---------------- batchnorm stats ----------------
__global__ void bn_stats_kernel(const float* __restrict__ in, float* __restrict__ mu,
                                float* __restrict__ rstd, int relu_flag) {
    __shared__ float shm[64];
    int c = blockIdx.x;
    float s = 0.f, s2 = 0.f;
    for (int i = threadIdx.x; i < BB*PIX; i += blockDim.x) {
        int b = i >> 10, p = i & 1023;
        float v = in[(b*CH + c)*PIX + p];
        if (relu_flag) v = fmaxf(v, 0.f);
        s += v; s2 += v*v;
    }
    block_reduce_2(s, s2, shm);
    if (threadIdx.x == 0) {
        float m = s / (float)(BB*PIX);
        float var = s2 / (float)(BB*PIX) - m*m;
        mu[c] = m;
        rstd[c] = rsqrtf(var + EPSV);
    }
}

__global__ void bn_apply_kernel(const float* __restrict__ in, const float* __restrict__ mu,
                                const float* __restrict__ rstd, const float* __restrict__ g,
                                const float* __restrict__ bta, float* __restrict__ out) {
    int idx = blockIdx.x*256 + threadIdx.x;
    if (idx >= BB*D) return;
    int c = (idx >> 10) % CH;
    out[idx] = (in[idx] - mu[c]) * rstd[c] * g[c] + bta[c];
}

// ---------------- conv1: 24->64 3x3 SAME + relu + gn1 stats
//                  optionally: z = sum(alpha_i * F_i), also written to xout ----------------
__global__ void __launch_bounds__(512, 1)
conv1_kernel(const float* __restrict__ z, const float* __restrict__ Fb,
             const float* __restrict__ al, float* __restrict__ xout,
             const float* __restrict__ w, float* __restrict__ t1,
             float* __restrict__ s1o) {
    extern __shared__ float s[];
    float* wd = s + IN1;
    __shared__ float gs[8], gq[8];
    int b = blockIdx.x, tid = threadIdx.x;
    const size_t SLOT = (size_t)BB * D;
    if (tid < 8) { gs[tid] = 0.f; gq[tid] = 0.f; }
    for (int i = tid; i < 64*24*9; i += 512) { float v = w[i]; wd[2*i] = v; wd[2*i+1] = v; }
    if (xout) {
        float a0=al[b*5+0], a1=al[b*5+1], a2=al[b*5+2], a3=al[b*5+3], a4=al[b*5+4];
        for (int i = tid; i < 24*1156; i += 512) {
            int c = i / 1156, rem = i % 1156, r = rem / 34, cx = rem % 34;
            float v = 0.f;
            if (r >= 1 && r <= 32 && cx >= 1 && cx <= 32) {
                size_t off = (size_t)(b*24 + c)*PIX + (r-1)*32 + (cx-1);
                v = a0*Fb[off] + a1*Fb[off + SLOT] + a2*Fb[off + 2*SLOT]
                  + a3*Fb[off + 3*SLOT] + a4*Fb[off + 4*SLOT];
                xout[off] = v;
            }
            s[c*(34*RS) + r*RS + cx] = v;
        }
    } else {
        for (int i = tid; i < 24*1156; i += 512) {
            int c = i / 1156, rem = i % 1156, r = rem / 34, cx = rem % 34;
            float v = 0.f;
            if (r >= 1 && r <= 32 && cx >= 1 && cx <= 32)
                v = z[(size_t)(b*24 + c)*PIX + (r-1)*32 + (cx-1)];
            s[c*(34*RS) + r*RS + cx] = v;
        }
    }
    __syncthreads();
    int ocg = tid >> 8, t = tid & 255, py = t >> 3, px0 = (t & 7) << 2;
    int lane = tid & 31;
#pragma unroll 1
    for (int tile = 0; tile < 2; tile++) {
        int oc0 = ocg*32 + tile*16;
        u64 A01[16], A23[16];
#pragma unroll
        for (int j = 0; j < 16; j++) { A01[j] = 0ull; A23[j] = 0ull; }
#pragma unroll 1
        for (int ic = 0; ic < 24; ic++)
#pragma unroll
            for (int ky = 0; ky < 3; ky++) {
                const float* row = &s[ic*(34*RS) + (py + ky)*RS + px0];
                float r0=row[0],r1=row[1],r2=row[2],r3=row[3],r4=row[4],r5=row[5];
                u64 p01=pk2(r0,r1), p12=pk2(r1,r2), p23=pk2(r2,r3),
                    p34=pk2(r3,r4), p45=pk2(r4,r5);
                const u64* wbase = (const u64*)&wd[(((size_t)oc0*24 + ic)*9 + ky*3)*2];
#pragma unroll
                for (int j = 0; j < 16; j++) {
                    const u64* wq = wbase + (size_t)j*216;
                    u64 W0 = wq[0], W1 = wq[1], W2 = wq[2];
                    FMA2(A01[j], p01, W0); FMA2(A01[j], p12, W1); FMA2(A01[j], p23, W2);
                    FMA2(A23[j], p23, W0); FMA2(A23[j], p34, W1); FMA2(A23[j], p45, W2);
                }
            }
        float sA=0.f, qA=0.f, sB=0.f, qB=0.f;
#pragma unroll
        for (int j = 0; j < 16; j++) {
            float2 v01 = upk2(A01[j]), v23 = upk2(A23[j]);
            float v0 = fmaxf(v01.x, 0.f), v1 = fmaxf(v01.y, 0.f);
            float v2 = fmaxf(v23.x, 0.f), v3 = fmaxf(v23.y, 0.f);
            float4 o; o.x=v0; o.y=v1; o.z=v2; o.w=v3;
            *(float4*)&t1[(size_t)(b*64 + oc0 + j)*PIX + py*32 + px0] = o;
            float ssv = v0+v1+v2+v3, qqv = v0*v0+v1*v1+v2*v2+v3*v3;
            if (j < 8) { sA += ssv; qA += qqv; } else { sB += ssv; qB += qqv; }
        }
#pragma unroll
        for (int o = 16; o > 0; o >>= 1) {
            sA += __shfl_down_sync(0xffffffffu, sA, o);
            qA += __shfl_down_sync(0xffffffffu, qA, o);
            sB += __shfl_down_sync(0xffffffffu, sB, o);
            qB += __shfl_down_sync(0xffffffffu, qB, o);
        }
        if (lane == 0) {
            int gA = oc0 >> 3;
            atomicAdd(&gs[gA], sA);     atomicAdd(&gq[gA], qA);
            atomicAdd(&gs[gA+1], sB);   atomicAdd(&gq[gA+1], qB);
        }
    }
    __syncthreads();
    if (tid < 8) {
        float m = gs[tid] * (1.f/8192.f);
        float var = gq[tid] * (1.f/8192.f) - m*m;
        s1o[b*16 + tid*2]     = m;
        s1o[b*16 + tid*2 + 1] = rsqrtf(var + EPSV);
    }
}

// ---------------- conv2: (gn1-affine on load) 64->24 3x3 SAME + xp, + gn2 stats ----------------
__global__ void __launch_bounds__(512, 1)
conv2_kernel(const float* __restrict__ t1, const float* __restrict__ w,
             const float* __restrict__ s1, const float* __restrict__ g1g,
             const float* __restrict__ g1b, const float* __restrict__ xp,
             float* __restrict__ t2, float* __restrict__ s2o) {
    extern __shared__ float s[];
    float* wd = s + IN2C;
    __shared__ float sc[64], bs[64], gs[8], gq[8];
    int b = blockIdx.x, tid = threadIdx.x;
    if (tid < 64) {
        int grp = tid >> 3;
        float m = s1[b*16 + grp*2], rs = s1[b*16 + grp*2 + 1];
        float gam = g1g[tid];
        sc[tid] = rs * gam;
        bs[tid] = g1b[tid] - m * rs * gam;
    }
    if (tid >= 64 && tid < 72) { gs[tid-64] = 0.f; gq[tid-64] = 0.f; }
    int ocg = tid >> 8, t = tid & 255, py = t >> 3, px0 = (t & 7) << 2;
    int lane = tid & 31;
    u64 A01[12], A23[12];
#pragma unroll
    for (int j = 0; j < 12; j++) { A01[j] = 0ull; A23[j] = 0ull; }
#pragma unroll 1
    for (int chunk = 0; chunk < 2; chunk++) {
        __syncthreads();
        int icb = chunk * 32;
        for (int i = tid; i < 24*32*9; i += 512) {
            int oc = i / 288, rem = i % 288, ic = rem / 9, k = rem % 9;
            float v = w[(oc*64 + icb + ic)*9 + k];
            wd[2*i] = v; wd[2*i+1] = v;
        }
        for (int i = tid; i < 32*1156; i += 512) {
            int c = i / 1156, rem = i % 1156, r = rem / 34, cx = rem % 34;
            float v = 0.f;
            if (r >= 1 && r <= 32 && cx >= 1 && cx <= 32) {
                int cg = icb + c;
                v = t1[(size_t)(b*64 + cg)*PIX + (r-1)*32 + (cx-1)] * sc[cg] + bs[cg];
            }
            s[c*(34*RS) + r*RS + cx] = v;
        }
        __syncthreads();
#pragma unroll 1
        for (int ic = 0; ic < 32; ic++)
#pragma unroll
            for (int ky = 0; ky < 3; ky++) {
                const float* row = &s[ic*(34*RS) + (py + ky)*RS + px0];
                float r0=row[0],r1=row[1],r2=row[2],r3=row[3],r4=row[4],r5=row[5];
                u64 p01=pk2(r0,r1), p12=pk2(r1,r2), p23=pk2(r2,r3),
                    p34=pk2(r3,r4), p45=pk2(r4,r5);
                const u64* wbase = (const u64*)&wd[(((size_t)(ocg*12)*32 + ic)*9 + ky*3)*2];
#pragma unroll
                for (int j = 0; j < 12; j++) {
                    const u64* wq = wbase + (size_t)j*288;
                    u64 W0 = wq[0], W1 = wq[1], W2 = wq[2];
                    FMA2(A01[j], p01, W0); FMA2(A01[j], p12, W1); FMA2(A01[j], p23, W2);
                    FMA2(A23[j], p23, W0); FMA2(A23[j], p34, W1); FMA2(A23[j], p45, W2);
                }
            }
    }
    float ss[4] = {0.f,0.f,0.f,0.f}, qq[4] = {0.f,0.f,0.f,0.f};
#pragma unroll
    for (int j = 0; j < 12; j++) {
        size_t idx = (size_t)(b*24 + ocg*12 + j)*PIX + py*32 + px0;
        float4 xv = *(const float4*)&xp[idx];
        float2 v01 = upk2(A01[j]), v23 = upk2(A23[j]);
        float v0 = v01.x + xv.x, v1 = v01.y + xv.y;
        float v2 = v23.x + xv.z, v3 = v23.y + xv.w;
        float4 o; o.x=v0; o.y=v1; o.z=v2; o.w=v3;
        *(float4*)&t2[idx] = o;
        int u = j / 3;
        ss[u] += v0+v1+v2+v3;
        qq[u] += v0*v0+v1*v1+v2*v2+v3*v3;
    }
#pragma unroll
    for (int o = 16; o > 0; o >>= 1)
#pragma unroll
        for (int u = 0; u < 4; u++) {
            ss[u] += __shfl_down_sync(0xffffffffu, ss[u], o);
            qq[u] += __shfl_down_sync(0xffffffffu, qq[u], o);
        }
    if (lane == 0)
#pragma unroll
        for (int u = 0; u < 4; u++) {
            atomicAdd(&gs[ocg*4 + u], ss[u]);
            atomicAdd(&gq[ocg*4 + u], qq[u]);
        }
    __syncthreads();
    if (tid < 8) {
        float m = gs[tid] * (1.f/3072.f);
        float var = gq[tid] * (1.f/3072.f) - m*m;
        s2o[b*16 + tid*2]     = m;
        s2o[b*16 + tid*2 + 1] = rsqrtf(var + EPSV);
    }
}

// ---------------- gn23: apply gn2 (stats precomputed) -> +z -> relu -> gn3 ----------------
__global__ void gn23_kernel(const float* __restrict__ t2, const float* __restrict__ z,
                            const float* __restrict__ s2, const float* __restrict__ g2,
                            const float* __restrict__ b2, const float* __restrict__ g3,
                            const float* __restrict__ b3, float* __restrict__ out) {
    __shared__ float buf[3072];
    __shared__ float shm[64];
    int b = blockIdx.x >> 3, grp = blockIdx.x & 7;
    int base = (b*24 + grp*3)*PIX;
    float m1 = s2[b*16 + grp*2], rs1 = s2[b*16 + grp*2 + 1];
    float s3 = 0.f, s4 = 0.f;
    for (int i = threadIdx.x; i < 3072; i += 256) {
        int c = grp*3 + (i >> 10);
        float u = (t2[base + i] - m1) * rs1 * g2[c] + b2[c];
        float v = fmaxf(z[base + i] + u, 0.f);
        buf[i] = v; s3 += v; s4 += v*v;
    }
    block_reduce_2(s3, s4, shm);
    float m2 = s3 / 3072.f;
    float rs2 = rsqrtf(s4 / 3072.f - m2*m2 + EPSV);
    for (int i = threadIdx.x; i < 3072; i += 256) {
        int c = grp*3 + (i >> 10);
        out[base + i] = (buf[i] - m2) * rs2 * g3[c] + b3[c];
    }
}

// ---------------- Anderson: Gram + fused 6x6 solve per batch ----------------
__global__ void hdot_solve_kernel(int n, const float* __restrict__ Fb,
                                  const float* __restrict__ Xb, float* __restrict__ alpha) {
    int b = blockIdx.x, tid = threadIdx.x;
    float acc[15];
#pragma unroll
    for (int i = 0; i < 15; i++) acc[i] = 0.f;
    size_t bd = (size_t)b * D;
    for (int d = tid; d < D; d += 256) {
        float gg[5];
#pragma unroll
        for (int i = 0; i < 5; i++) {
            size_t off = (size_t)i * (BB*(size_t)D) + bd + d;
            gg[i] = (i < n) ? (Fb[off] - Xb[off]) : 0.f;
        }
        int idx = 0;
#pragma unroll
        for (int i = 0; i < 5; i++)
#pragma unroll
            for (int j = i; j < 5; j++) { acc[idx] += gg[i]*gg[j]; idx++; }
    }
    __shared__ float sh[8][15];
    __shared__ float Hs[15];
    int lane = tid & 31, wid = tid >> 5;
#pragma unroll
    for (int p = 0; p < 15; p++) {
        float v = acc[p];
#pragma unroll
        for (int o = 16; o > 0; o >>= 1) v += __shfl_down_sync(0xffffffffu, v, o);
        if (lane == 0) sh[wid][p] = v;
    }
    __syncthreads();
    if (tid < 15) {
        float v = 0.f;
#pragma unroll
        for (int wq = 0; wq < 8; wq++) v += sh[wq][tid];
        Hs[tid] = v;
    }
    __syncthreads();
    if (tid == 0) {
        float Hm[5][5];
        int idx = 0;
        for (int i = 0; i < 5; i++)
            for (int j = i; j < 5; j++) { Hm[i][j] = Hs[idx]; Hm[j][i] = Hs[idx]; idx++; }
        int m = n + 1;
        float A[6][7];
        for (int i = 0; i < m; i++)
            for (int j = 0; j <= m; j++) A[i][j] = 0.f;
        for (int j = 1; j < m; j++) { A[0][j] = 1.f; A[j][0] = 1.f; }
        for (int i = 0; i < n; i++)
            for (int j = 0; j < n; j++)
                A[i+1][j+1] = Hm[i][j] + ((i == j) ? LAMV : 0.f);
        A[0][m] = 1.f;
        for (int col = 0; col < m; col++) {
            int piv = col; float best = fabsf(A[col][col]);
            for (int r = col + 1; r < m; r++) {
                float v = fabsf(A[r][col]);
                if (v > best) { best = v; piv = r; }
            }
            if (piv != col)
                for (int j = col; j <= m; j++) { float tv = A[col][j]; A[col][j] = A[piv][j]; A[piv][j] = tv; }
            float inv = 1.f / A[col][col];
            for (int r = col + 1; r < m; r++) {
                float f = A[r][col] * inv;
                for (int j = col; j <= m; j++) A[r][j] -= f * A[col][j];
            }
        }
        float xs[6];
        for (int i = m - 1; i >= 0; i--) {
            float v = A[i][m];
            for (int j = i + 1; j < m; j++) v -= A[i][j] * xs[j];
            xs[i] = v / A[i][i];
        }
        for (int i = 0; i < 5; i++) alpha[b*5 + i] = (i < n) ? xs[i + 1] : 0.f;
    }
}

// ---------------- post: relu -> BN apply -> 8x8 avgpool ----------------
__global__ void pool_kernel(const float* __restrict__ z, const float* __restrict__ mu,
                            const float* __restrict__ rstd, const float* __restrict__ g,
                            const float* __restrict__ bta, float* __restrict__ pooled) {
    __shared__ float pl[16];
    int b = blockIdx.x / 24, c = blockIdx.x % 24;
    if (threadIdx.x < 16) pl[threadIdx.x] = 0.f;
    __syncthreads();
    float mc = mu[c], rc = rstd[c], gc = g[c], bc = bta[c];
    for (int i = threadIdx.x; i < 1024; i += 256) {
        int yy = i >> 5, xx = i & 31;
        float v = fmaxf(z[(b*24 + c)*PIX + i], 0.f);
        v = (v - mc) * rc * gc + bc;
        atomicAdd(&pl[(yy >> 3)*4 + (xx >> 3)], v);
    }
    __syncthreads();
    if (threadIdx.x < 16)
        pooled[(b*24 + c)*16 + threadIdx.x] = pl[threadIdx.x] * (1.f/64.f);
}

// ---------------- final FC ----------------
__global__ void fc_kernel(const float* __restrict__ pooled, const float* __restrict__ w,
                          const float* __restrict__ bias, float* __restrict__ out) {
    int b = blockIdx.x;
    int warp = threadIdx.x >> 5, lane = threadIdx.x & 31;
    float acc = 0.f;
    for (int k = lane; k < 384; k += 32)
        acc += pooled[b*384 + k] * w[warp*384 + k];
#pragma unroll
    for (int o = 16; o > 0; o >>= 1) acc += __shfl_down_sync(0xffffffffu, acc, o);
    if (lane == 0) out[b*10 + warp] = acc + bias[warp];
}

// ---------------- host orchestration ----------------
extern "C" void kernel_launch(void* const* d_in, const int* in_sizes, int n_in,
                              void* d_out, int out_size) {
    const float* x     = (const float*)d_in[0];
    const float* pw    = (const float*)d_in[1];
    const float* pbia  = (const float*)d_in[2];
    const float* pbn_g = (const float*)d_in[3];
    const float* pbn_b = (const float*)d_in[4];
    const float* w1    = (const float*)d_in[5];
    const float* g1g   = (const float*)d_in[6];
    const float* g1b   = (const float*)d_in[7];
    const float* w2    = (const float*)d_in[8];
    const float* g2g   = (const float*)d_in[9];
    const float* g2b   = (const float*)d_in[10];
    const float* g3g   = (const float*)d_in[11];
    const float* g3b   = (const float*)d_in[12];
    const float* qbn_g = (const float*)d_in[13];
    const float* qbn_b = (const float*)d_in[14];
    const float* fcw   = (const float*)d_in[15];
    const float* fcb   = (const float*)d_in[16];
    float* out = (float*)d_out;

    static bool attr_done = false;
    if (!attr_done) {
        cudaFuncSetAttribute(conv1_kernel, cudaFuncAttributeMaxDynamicSharedMemorySize, SMEM1);
        cudaFuncSetAttribute(conv2_kernel, cudaFuncAttributeMaxDynamicSharedMemorySize, SMEM2);
        attr_done = true;
    }

    float *Xb, *Fb, *xp, *pre, *t1, *t2, *al, *s1, *s2;
    float *bmu, *brs, *pmu, *prs, *pl;
    cudaGetSymbolAddress((void**)&Xb,  g_X);
    cudaGetSymbolAddress((void**)&Fb,  g_F);
    cudaGetSymbolAddress((void**)&xp,  g_xp);
    cudaGetSymbolAddress((void**)&pre, g_pre);
    cudaGetSymbolAddress((void**)&t1,  g_t1);
    cudaGetSymbolAddress((void**)&t2,  g_t2);
    cudaGetSymbolAddress((void**)&al,  g_al);
    cudaGetSymbolAddress((void**)&s1,  g_s1);
    cudaGetSymbolAddress((void**)&s2,  g_s2);
    cudaGetSymbolAddress((void**)&bmu, g_bmu);
    cudaGetSymbolAddress((void**)&brs, g_brs);
    cudaGetSymbolAddress((void**)&pmu, g_pmu);
    cudaGetSymbolAddress((void**)&prs, g_prs);
    cudaGetSymbolAddress((void**)&pl,  g_pool);

    const size_t SLOT = (size_t)BB * D;

    preconv_kernel<<<128, 256>>>(x, pw, pbia, pre);
    bn_stats_kernel<<<24, 512>>>(pre, bmu, brs, 0);
    bn_apply_kernel<<<(BB*D + 255)/256, 256>>>(pre, bmu, brs, pbn_g, pbn_b, xp);

    cudaMemsetAsync(Xb, 0, SLOT * sizeof(float));

    auto runf = [&](const float* z, float* xo, float* fo) {
        conv1_kernel<<<128, 512, SMEM1>>>(z, Fb, al, xo, w1, t1, s1);
        conv2_kernel<<<128, 512, SMEM2>>>(t1, w2, s1, g1g, g1b, xp, t2, s2);
        const float* zz = xo ? xo : z;
        gn23_kernel<<<1024, 256>>>(t2, zz, s2, g2g, g2b, g3g, g3b, fo);
    };

    runf(Xb, nullptr, Fb);                                        // F0 = f(0)
    cudaMemcpyAsync(Xb + SLOT, Fb, SLOT * sizeof(float), cudaMemcpyDeviceToDevice);
    runf(Xb + SLOT, nullptr, Fb + SLOT);                          // F1 = f(F0)

    for (int k = 2; k < 25; k++) {
        int n = (k < 5) ? k : 5;
        size_t slt = (size_t)(k % 5);
        hdot_solve_kernel<<<128, 256>>>(n, Fb, Xb, al);
        runf(nullptr, Xb + slt*SLOT, Fb + slt*SLOT);              // conv1 builds z & X slot
    }

    const float* zf = Fb + 4 * SLOT;   // z = f(z_star) = F[:,4]

    bn_stats_kernel<<<24, 512>>>(zf, pmu, prs, 1);
    pool_kernel<<<128*24, 256>>>(zf, pmu, prs, qbn_g, qbn_b, pl);
    fc_kernel<<<128, 320>>>(pl, fcw, fcb, out);
}

// round 4
// speedup vs baseline: 1.0461x; 1.0461x over previous
#include <cuda_runtime.h>
#include <cuda_bf16.h>
#include <math.h>

#define BB   128
#define CH   24
#define PIX  1024
#define D    (CH*PIX)
#define MM   5
#define EPSV 1e-5f
#define LAMV 1e-4f

#define RS    35                      // padded row stride (conflict-free)
#define IN1   (24*34*RS)              // 28560 floats
#define W1SZ  (64*24*9)               // 13824 floats
#define SMEM1 ((IN1 + W1SZ)*4)        // 169536 B

#define IN2C  (32*34*RS)              // 38080 floats (one 32-ic chunk, full image)
#define W2SZ  (24*32*9)               // 6912 floats
#define SMEM2 ((IN2C + W2SZ)*4)       // 179968 B

// ---------------- device scratch ----------------
__device__ float g_pre [BB*D];
__device__ float g_xp  [BB*D];
__device__ float g_X   [MM*BB*D];
__device__ float g_F   [MM*BB*D];
__device__ float g_t1  [BB*64*PIX];
__device__ float g_t2  [BB*D];
__device__ float g_al  [BB*MM];
__device__ float g_s1  [BB*16];        // gn1 per-(b,grp): mean, rstd
__device__ float g_s2  [BB*16];        // gn2 per-(b,grp): mean, rstd
__device__ float g_bmu [CH];
__device__ float g_brs [CH];
__device__ float g_pmu [CH];
__device__ float g_prs [CH];
__device__ float g_pool[BB*CH*16];

// ---------------- block reduce (sum, sumsq) ----------------
__device__ __forceinline__ void block_reduce_2(float& s, float& s2, float* shm) {
    __syncthreads();
    int lane = threadIdx.x & 31, wid = threadIdx.x >> 5;
#pragma unroll
    for (int o = 16; o > 0; o >>= 1) {
        s  += __shfl_down_sync(0xffffffffu, s,  o);
        s2 += __shfl_down_sync(0xffffffffu, s2, o);
    }
    if (lane == 0) { shm[wid] = s; shm[32 + wid] = s2; }
    __syncthreads();
    int nw = (blockDim.x + 31) >> 5;
    if (wid == 0) {
        s  = (lane < nw) ? shm[lane]      : 0.f;
        s2 = (lane < nw) ? shm[32 + lane] : 0.f;
#pragma unroll
        for (int o = 16; o > 0; o >>= 1) {
            s  += __shfl_down_sync(0xffffffffu, s,  o);
            s2 += __shfl_down_sync(0xffffffffu, s2, o);
        }
        if (lane == 0) { shm[0] = s; shm[32] = s2; }
    }
    __syncthreads();
    s = shm[0]; s2 = shm[32];
}

// ---------------- pre conv 3->24 (+bias) ----------------
__global__ void preconv_kernel(const float* __restrict__ x, const float* __restrict__ w,
                               const float* __restrict__ bias, float* __restrict__ out) {
    __shared__ float s[3*34*34];
    int b = blockIdx.x, tid = threadIdx.x;
    for (int i = tid; i < 3*1156; i += 256) {
        int c = i / 1156, rem = i % 1156, r = rem / 34, cx = rem % 34;
        float v = 0.f;
        if (r >= 1 && r <= 32 && cx >= 1 && cx <= 32)
            v = x[((b*3 + c)*32 + (r-1))*32 + (cx-1)];
        s[i] = v;
    }
    __syncthreads();
    int py = tid >> 3, px0 = (tid & 7) << 2;
    for (int oc0 = 0; oc0 < 24; oc0 += 8) {
        float acc[8][4];
#pragma unroll
        for (int j = 0; j < 8; j++) {
            float bv = __ldg(&bias[oc0 + j]);
#pragma unroll
            for (int p = 0; p < 4; p++) acc[j][p] = bv;
        }
        for (int ic = 0; ic < 3; ic++)
#pragma unroll
            for (int ky = 0; ky < 3; ky++) {
                const float* row = &s[ic*1156 + (py + ky)*34 + px0];
                float r0=row[0],r1=row[1],r2=row[2],r3=row[3],r4=row[4],r5=row[5];
#pragma unroll
                for (int j = 0; j < 8; j++) {
                    int oc = oc0 + j;
                    const float* wq = &w[((oc*3 + ic)*3 + ky)*3];
                    float w0=__ldg(wq), w1=__ldg(wq+1), w2=__ldg(wq+2);
                    acc[j][0] += r0*w0 + r1*w1 + r2*w2;
                    acc[j][1] += r1*w0 + r2*w1 + r3*w2;
                    acc[j][2] += r2*w0 + r3*w1 + r4*w2;
                    acc[j][3] += r3*w0 + r4*w1 + r5*w2;
                }
            }
#pragma unroll
        for (int j = 0; j < 8; j++)
#pragma unroll
            for (int p = 0; p < 4; p++)
                out[(b*24 + oc0 + j)*PIX + py*32 + px0 + p] = acc[j][p];
    }
}

// ---------------- batchnorm stats ----------------
__global__ void bn_stats_kernel(const float* __restrict__ in, float* __restrict__ mu,
                                float* __restrict__ rstd, int relu_flag) {
    __shared__ float shm[64];
    int c = blockIdx.x;
    float s = 0.f, s2 = 0.f;
    for (int i = threadIdx.x; i < BB*PIX; i += blockDim.x) {
        int b = i >> 10, p = i & 1023;
        float v = in[(b*CH + c)*PIX + p];
        if (relu_flag) v = fmaxf(v, 0.f);
        s += v; s2 += v*v;
    }
    block_reduce_2(s, s2, shm);
    if (threadIdx.x == 0) {
        float m = s / (float)(BB*PIX);
        float var = s2 / (float)(BB*PIX) - m*m;
        mu[c] = m;
        rstd[c] = rsqrtf(var + EPSV);
    }
}

__global__ void bn_apply_kernel(const float* __restrict__ in, const float* __restrict__ mu,
                                const float* __restrict__ rstd, const float* __restrict__ g,
                                const float* __restrict__ bta, float* __restrict__ out) {
    int idx = blockIdx.x*256 + threadIdx.x;
    if (idx >= BB*D) return;
    int c = (idx >> 10) % CH;
    out[idx] = (in[idx] - mu[c]) * rstd[c] * g[c] + bta[c];
}

// ---------------- conv1: 24->64 3x3 SAME + relu + gn1 stats
//   optional fused Anderson combine: z = sum(alpha_i F_i), written to xout ----------------
__global__ void __launch_bounds__(512, 1)
conv1_kernel(const float* __restrict__ z, const float* __restrict__ Fb,
             const float* __restrict__ al, float* __restrict__ xout,
             const float* __restrict__ w, float* __restrict__ t1,
             float* __restrict__ s1o) {
    extern __shared__ float s[];
    float* ws = s + IN1;
    __shared__ float gs[8], gq[8];
    int b = blockIdx.x, tid = threadIdx.x;
    const size_t SLOT = (size_t)BB * D;
    if (tid < 8) { gs[tid] = 0.f; gq[tid] = 0.f; }
    for (int i = tid; i < W1SZ; i += 512) ws[i] = w[i];
    if (xout) {
        float a0=al[b*5+0], a1=al[b*5+1], a2=al[b*5+2], a3=al[b*5+3], a4=al[b*5+4];
        for (int i = tid; i < 24*1156; i += 512) {
            int c = i / 1156, rem = i % 1156, r = rem / 34, cx = rem % 34;
            float v = 0.f;
            if (r >= 1 && r <= 32 && cx >= 1 && cx <= 32) {
                size_t off = (size_t)(b*24 + c)*PIX + (r-1)*32 + (cx-1);
                v = a0*Fb[off] + a1*Fb[off + SLOT] + a2*Fb[off + 2*SLOT]
                  + a3*Fb[off + 3*SLOT] + a4*Fb[off + 4*SLOT];
                xout[off] = v;
            }
            s[c*(34*RS) + r*RS + cx] = v;
        }
    } else {
        for (int i = tid; i < 24*1156; i += 512) {
            int c = i / 1156, rem = i % 1156, r = rem / 34, cx = rem % 34;
            float v = 0.f;
            if (r >= 1 && r <= 32 && cx >= 1 && cx <= 32)
                v = z[(size_t)(b*24 + c)*PIX + (r-1)*32 + (cx-1)];
            s[c*(34*RS) + r*RS + cx] = v;
        }
    }
    __syncthreads();
    int ocg = tid >> 7;                    // 0..3
    int t = tid & 127;
    int py = t >> 2, px0 = (t & 3) << 3;   // py 0..31, px0 {0,8,16,24}
    int lane = tid & 31;
#pragma unroll 1
    for (int tile = 0; tile < 2; tile++) {
        int oc0 = tile*32 + ocg*8;         // one full gn1 group (8 channels)
        float acc[8][8];
#pragma unroll
        for (int j = 0; j < 8; j++)
#pragma unroll
            for (int p = 0; p < 8; p++) acc[j][p] = 0.f;
#pragma unroll 1
        for (int ic = 0; ic < 24; ic++)
#pragma unroll
            for (int ky = 0; ky < 3; ky++) {
                const float* row = &s[ic*(34*RS) + (py + ky)*RS + px0];
                float r[10];
#pragma unroll
                for (int p = 0; p < 10; p++) r[p] = row[p];
#pragma unroll
                for (int j = 0; j < 8; j++) {
                    const float* wq = &ws[((oc0 + j)*24 + ic)*9 + ky*3];
                    float w0=wq[0], w1=wq[1], w2=wq[2];
#pragma unroll
                    for (int p = 0; p < 8; p++)
                        acc[j][p] += r[p]*w0 + r[p+1]*w1 + r[p+2]*w2;
                }
            }
        float ss = 0.f, qq = 0.f;
#pragma unroll
        for (int j = 0; j < 8; j++) {
            float v[8];
#pragma unroll
            for (int p = 0; p < 8; p++) {
                v[p] = fmaxf(acc[j][p], 0.f);
                ss += v[p]; qq += v[p]*v[p];
            }
            float4 o0; o0.x=v[0]; o0.y=v[1]; o0.z=v[2]; o0.w=v[3];
            float4 o1; o1.x=v[4]; o1.y=v[5]; o1.z=v[6]; o1.w=v[7];
            float* dst = &t1[(size_t)(b*64 + oc0 + j)*PIX + py*32 + px0];
            *(float4*)dst = o0;
            *(float4*)(dst + 4) = o1;
        }
#pragma unroll
        for (int o = 16; o > 0; o >>= 1) {
            ss += __shfl_down_sync(0xffffffffu, ss, o);
            qq += __shfl_down_sync(0xffffffffu, qq, o);
        }
        if (lane == 0) {
            int grp = oc0 >> 3;
            atomicAdd(&gs[grp], ss);
            atomicAdd(&gq[grp], qq);
        }
    }
    __syncthreads();
    if (tid < 8) {
        float m = gs[tid] * (1.f/8192.f);
        float var = gq[tid] * (1.f/8192.f) - m*m;
        s1o[b*16 + tid*2]     = m;
        s1o[b*16 + tid*2 + 1] = rsqrtf(var + EPSV);
    }
}

// ---------------- conv2: gn1-affine on load, 64->24 3x3 SAME + xp, gn2 stats ----------------
__global__ void __launch_bounds__(512, 1)
conv2_kernel(const float* __restrict__ t1, const float* __restrict__ w,
             const float* __restrict__ s1, const float* __restrict__ g1g,
             const float* __restrict__ g1b, const float* __restrict__ xp,
             float* __restrict__ t2, float* __restrict__ s2o) {
    extern __shared__ float s[];
    float* ws = s + IN2C;
    __shared__ float sc[64], bs[64], gs[8], gq[8];
    int b = blockIdx.x, tid = threadIdx.x;
    if (tid < 64) {
        int grp = tid >> 3;
        float m = s1[b*16 + grp*2], rs = s1[b*16 + grp*2 + 1];
        float gam = g1g[tid];
        sc[tid] = rs * gam;
        bs[tid] = g1b[tid] - m * rs * gam;
    }
    if (tid >= 64 && tid < 72) { gs[tid-64] = 0.f; gq[tid-64] = 0.f; }
    int ocg = tid >> 7;                    // 0..3 -> 6 oc each
    int t = tid & 127;
    int py = t >> 2, px0 = (t & 3) << 3;
    int lane = tid & 31;
    float acc[6][8];
#pragma unroll
    for (int j = 0; j < 6; j++)
#pragma unroll
        for (int p = 0; p < 8; p++) acc[j][p] = 0.f;
#pragma unroll 1
    for (int chunk = 0; chunk < 2; chunk++) {
        __syncthreads();
        int icb = chunk * 32;
        for (int i = tid; i < 24*32*9; i += 512) {
            int oc = i / 288, rem = i % 288, ic = rem / 9, k = rem % 9;
            ws[i] = w[(oc*64 + icb + ic)*9 + k];
        }
        for (int i = tid; i < 32*1156; i += 512) {
            int c = i / 1156, rem = i % 1156, r = rem / 34, cx = rem % 34;
            float v = 0.f;
            if (r >= 1 && r <= 32 && cx >= 1 && cx <= 32) {
                int cg = icb + c;
                v = t1[(size_t)(b*64 + cg)*PIX + (r-1)*32 + (cx-1)] * sc[cg] + bs[cg];
            }
            s[c*(34*RS) + r*RS + cx] = v;
        }
        __syncthreads();
#pragma unroll 1
        for (int ic = 0; ic < 32; ic++)
#pragma unroll
            for (int ky = 0; ky < 3; ky++) {
                const float* row = &s[ic*(34*RS) + (py + ky)*RS + px0];
                float r[10];
#pragma unroll
                for (int p = 0; p < 10; p++) r[p] = row[p];
#pragma unroll
                for (int j = 0; j < 6; j++) {
                    const float* wq = &ws[((ocg*6 + j)*32 + ic)*9 + ky*3];
                    float w0=wq[0], w1=wq[1], w2=wq[2];
#pragma unroll
                    for (int p = 0; p < 8; p++)
                        acc[j][p] += r[p]*w0 + r[p+1]*w1 + r[p+2]*w2;
                }
            }
    }
    float ss[2] = {0.f, 0.f}, qq[2] = {0.f, 0.f};
#pragma unroll
    for (int j = 0; j < 6; j++) {
        size_t idx = (size_t)(b*24 + ocg*6 + j)*PIX + py*32 + px0;
        float4 x0 = *(const float4*)&xp[idx];
        float4 x1 = *(const float4*)&xp[idx + 4];
        float v[8];
        v[0]=acc[j][0]+x0.x; v[1]=acc[j][1]+x0.y; v[2]=acc[j][2]+x0.z; v[3]=acc[j][3]+x0.w;
        v[4]=acc[j][4]+x1.x; v[5]=acc[j][5]+x1.y; v[6]=acc[j][6]+x1.z; v[7]=acc[j][7]+x1.w;
        float4 o0; o0.x=v[0]; o0.y=v[1]; o0.z=v[2]; o0.w=v[3];
        float4 o1; o1.x=v[4]; o1.y=v[5]; o1.z=v[6]; o1.w=v[7];
        *(float4*)&t2[idx] = o0;
        *(float4*)&t2[idx + 4] = o1;
        int u = j / 3;                       // gn2 group within this ocg (3 ch/group)
        float sv = 0.f, qv = 0.f;
#pragma unroll
        for (int p = 0; p < 8; p++) { sv += v[p]; qv += v[p]*v[p]; }
        ss[u] += sv; qq[u] += qv;
    }
#pragma unroll
    for (int o = 16; o > 0; o >>= 1)
#pragma unroll
        for (int u = 0; u < 2; u++) {
            ss[u] += __shfl_down_sync(0xffffffffu, ss[u], o);
            qq[u] += __shfl_down_sync(0xffffffffu, qq[u], o);
        }
    if (lane == 0)
#pragma unroll
        for (int u = 0; u < 2; u++) {
            atomicAdd(&gs[ocg*2 + u], ss[u]);
            atomicAdd(&gq[ocg*2 + u], qq[u]);
        }
    __syncthreads();
    if (tid < 8) {
        float m = gs[tid] * (1.f/3072.f);
        float var = gq[tid] * (1.f/3072.f) - m*m;
        s2o[b*16 + tid*2]     = m;
        s2o[b*16 + tid*2 + 1] = rsqrtf(var + EPSV);
    }
}

// ---------------- gn23: apply gn2 (stats precomputed) -> +z -> relu -> gn3 ----------------
__global__ void gn23_kernel(const float* __restrict__ t2, const float* __restrict__ z,
                            const float* __restrict__ s2, const float* __restrict__ g2,
                            const float* __restrict__ b2, const float* __restrict__ g3,
                            const float* __restrict__ b3, float* __restrict__ out) {
    __shared__ float buf[3072];
    __shared__ float shm[64];
    int b = blockIdx.x >> 3, grp = blockIdx.x & 7;
    int base = (b*24 + grp*3)*PIX;
    float m1 = s2[b*16 + grp*2], rs1 = s2[b*16 + grp*2 + 1];
    float s3 = 0.f, s4 = 0.f;
    for (int i = threadIdx.x; i < 3072; i += 256) {
        int c = grp*3 + (i >> 10);
        float u = (t2[base + i] - m1) * rs1 * g2[c] + b2[c];
        float v = fmaxf(z[base + i] + u, 0.f);
        buf[i] = v; s3 += v; s4 += v*v;
    }
    block_reduce_2(s3, s4, shm);
    float m2 = s3 / 3072.f;
    float rs2 = rsqrtf(s4 / 3072.f - m2*m2 + EPSV);
    for (int i = threadIdx.x; i < 3072; i += 256) {
        int c = grp*3 + (i >> 10);
        out[base + i] = (buf[i] - m2) * rs2 * g3[c] + b3[c];
    }
}

// ---------------- Anderson: Gram + fused 6x6 solve per batch ----------------
__global__ void hdot_solve_kernel(int n, const float* __restrict__ Fb,
                                  const float* __restrict__ Xb, float* __restrict__ alpha) {
    int b = blockIdx.x, tid = threadIdx.x;
    float acc[15];
#pragma unroll
    for (int i = 0; i < 15; i++) acc[i] = 0.f;
    size_t bd = (size_t)b * D;
    for (int d = tid; d < D; d += 256) {
        float gg[5];
#pragma unroll
        for (int i = 0; i < 5; i++) {
            size_t off = (size_t)i * (BB*(size_t)D) + bd + d;
            gg[i] = (i < n) ? (Fb[off] - Xb[off]) : 0.f;
        }
        int idx = 0;
#pragma unroll
        for (int i = 0; i < 5; i++)
#pragma unroll
            for (int j = i; j < 5; j++) { acc[idx] += gg[i]*gg[j]; idx++; }
    }
    __shared__ float sh[8][15];
    __shared__ float Hs[15];
    int lane = tid & 31, wid = tid >> 5;
#pragma unroll
    for (int p = 0; p < 15; p++) {
        float v = acc[p];
#pragma unroll
        for (int o = 16; o > 0; o >>= 1) v += __shfl_down_sync(0xffffffffu, v, o);
        if (lane == 0) sh[wid][p] = v;
    }
    __syncthreads();
    if (tid < 15) {
        float v = 0.f;
#pragma unroll
        for (int wq = 0; wq < 8; wq++) v += sh[wq][tid];
        Hs[tid] = v;
    }
    __syncthreads();
    if (tid == 0) {
        float Hm[5][5];
        int idx = 0;
        for (int i = 0; i < 5; i++)
            for (int j = i; j < 5; j++) { Hm[i][j] = Hs[idx]; Hm[j][i] = Hs[idx]; idx++; }
        int m = n + 1;
        float A[6][7];
        for (int i = 0; i < m; i++)
            for (int j = 0; j <= m; j++) A[i][j] = 0.f;
        for (int j = 1; j < m; j++) { A[0][j] = 1.f; A[j][0] = 1.f; }
        for (int i = 0; i < n; i++)
            for (int j = 0; j < n; j++)
                A[i+1][j+1] = Hm[i][j] + ((i == j) ? LAMV : 0.f);
        A[0][m] = 1.f;
        for (int col = 0; col < m; col++) {
            int piv = col; float best = fabsf(A[col][col]);
            for (int r = col + 1; r < m; r++) {
                float v = fabsf(A[r][col]);
                if (v > best) { best = v; piv = r; }
            }
            if (piv != col)
                for (int j = col; j <= m; j++) { float tv = A[col][j]; A[col][j] = A[piv][j]; A[piv][j] = tv; }
            float inv = 1.f / A[col][col];
            for (int r = col + 1; r < m; r++) {
                float f = A[r][col] * inv;
                for (int j = col; j <= m; j++) A[r][j] -= f * A[col][j];
            }
        }
        float xs[6];
        for (int i = m - 1; i >= 0; i--) {
            float v = A[i][m];
            for (int j = i + 1; j < m; j++) v -= A[i][j] * xs[j];
            xs[i] = v / A[i][i];
        }
        for (int i = 0; i < 5; i++) alpha[b*5 + i] = (i < n) ? xs[i + 1] : 0.f;
    }
}

// ---------------- post: relu -> BN apply -> 8x8 avgpool ----------------
__global__ void pool_kernel(const float* __restrict__ z, const float* __restrict__ mu,
                            const float* __restrict__ rstd, const float* __restrict__ g,
                            const float* __restrict__ bta, float* __restrict__ pooled) {
    __shared__ float pl[16];
    int b = blockIdx.x / 24, c = blockIdx.x % 24;
    if (threadIdx.x < 16) pl[threadIdx.x] = 0.f;
    __syncthreads();
    float mc = mu[c], rc = rstd[c], gc = g[c], bc = bta[c];
    for (int i = threadIdx.x; i < 1024; i += 256) {
        int yy = i >> 5, xx = i & 31;
        float v = fmaxf(z[(b*24 + c)*PIX + i], 0.f);
        v = (v - mc) * rc * gc + bc;
        atomicAdd(&pl[(yy >> 3)*4 + (xx >> 3)], v);
    }
    __syncthreads();
    if (threadIdx.x < 16)
        pooled[(b*24 + c)*16 + threadIdx.x] = pl[threadIdx.x] * (1.f/64.f);
}

// ---------------- final FC ----------------
__global__ void fc_kernel(const float* __restrict__ pooled, const float* __restrict__ w,
                          const float* __restrict__ bias, float* __restrict__ out) {
    int b = blockIdx.x;
    int warp = threadIdx.x >> 5, lane = threadIdx.x & 31;
    float acc = 0.f;
    for (int k = lane; k < 384; k += 32)
        acc += pooled[b*384 + k] * w[warp*384 + k];
#pragma unroll
    for (int o = 16; o > 0; o >>= 1) acc += __shfl_down_sync(0xffffffffu, acc, o);
    if (lane == 0) out[b*10 + warp] = acc + bias[warp];
}

// ---------------- host orchestration ----------------
extern "C" void kernel_launch(void* const* d_in, const int* in_sizes, int n_in,
                              void* d_out, int out_size) {
    const float* x     = (const float*)d_in[0];
    const float* pw    = (const float*)d_in[1];
    const float* pbia  = (const float*)d_in[2];
    const float* pbn_g = (const float*)d_in[3];
    const float* pbn_b = (const float*)d_in[4];
    const float* w1    = (const float*)d_in[5];
    const float* g1g   = (const float*)d_in[6];
    const float* g1b   = (const float*)d_in[7];
    const float* w2    = (const float*)d_in[8];
    const float* g2g   = (const float*)d_in[9];
    const float* g2b   = (const float*)d_in[10];
    const float* g3g   = (const float*)d_in[11];
    const float* g3b   = (const float*)d_in[12];
    const float* qbn_g = (const float*)d_in[13];
    const float* qbn_b = (const float*)d_in[14];
    const float* fcw   = (const float*)d_in[15];
    const float* fcb   = (const float*)d_in[16];
    float* out = (float*)d_out;

    static bool attr_done = false;
    if (!attr_done) {
        cudaFuncSetAttribute(conv1_kernel, cudaFuncAttributeMaxDynamicSharedMemorySize, SMEM1);
        cudaFuncSetAttribute(conv2_kernel, cudaFuncAttributeMaxDynamicSharedMemorySize, SMEM2);
        attr_done = true;
    }

    float *Xb, *Fb, *xp, *pre, *t1, *t2, *al, *s1, *s2;
    float *bmu, *brs, *pmu, *prs, *pl;
    cudaGetSymbolAddress((void**)&Xb,  g_X);
    cudaGetSymbolAddress((void**)&Fb,  g_F);
    cudaGetSymbolAddress((void**)&xp,  g_xp);
    cudaGetSymbolAddress((void**)&pre, g_pre);
    cudaGetSymbolAddress((void**)&t1,  g_t1);
    cudaGetSymbolAddress((void**)&t2,  g_t2);
    cudaGetSymbolAddress((void**)&al,  g_al);
    cudaGetSymbolAddress((void**)&s1,  g_s1);
    cudaGetSymbolAddress((void**)&s2,  g_s2);
    cudaGetSymbolAddress((void**)&bmu, g_bmu);
    cudaGetSymbolAddress((void**)&brs, g_brs);
    cudaGetSymbolAddress((void**)&pmu, g_pmu);
    cudaGetSymbolAddress((void**)&prs, g_prs);
    cudaGetSymbolAddress((void**)&pl,  g_pool);

    const size_t SLOT = (size_t)BB * D;

    preconv_kernel<<<128, 256>>>(x, pw, pbia, pre);
    bn_stats_kernel<<<24, 512>>>(pre, bmu, brs, 0);
    bn_apply_kernel<<<(BB*D + 255)/256, 256>>>(pre, bmu, brs, pbn_g, pbn_b, xp);

    cudaMemsetAsync(Xb, 0, SLOT * sizeof(float));

    auto runf = [&](const float* z, float* xo, float* fo) {
        conv1_kernel<<<128, 512, SMEM1>>>(z, Fb, al, xo, w1, t1, s1);
        conv2_kernel<<<128, 512, SMEM2>>>(t1, w2, s1, g1g, g1b, xp, t2, s2);
        const float* zz = xo ? xo : z;
        gn23_kernel<<<1024, 256>>>(t2, zz, s2, g2g, g2b, g3g, g3b, fo);
    };

    runf(Xb, nullptr, Fb);                                        // F0 = f(0)
    cudaMemcpyAsync(Xb + SLOT, Fb, SLOT * sizeof(float), cudaMemcpyDeviceToDevice);
    runf(Xb + SLOT, nullptr, Fb + SLOT);                          // F1 = f(F0)

    for (int k = 2; k < 25; k++) {
        int n = (k < 5) ? k : 5;
        size_t slt = (size_t)(k % 5);
        hdot_solve_kernel<<<128, 256>>>(n, Fb, Xb, al);
        runf(nullptr, Xb + slt*SLOT, Fb + slt*SLOT);              // conv1 builds z & X slot
    }

    const float* zf = Fb + 4 * SLOT;   // z = f(z_star) = F[:,4]

    bn_stats_kernel<<<24, 512>>>(zf, pmu, prs, 1);
    pool_kernel<<<128*24, 256>>>(zf, pmu, prs, qbn_g, qbn_b, pl);
    fc_kernel<<<128, 320>>>(pl, fcw, fcb, out);
}

// round 5
// speedup vs baseline: 1.6942x; 1.6196x over previous
#include <cuda_runtime.h>
#include <cuda_bf16.h>
#include <math.h>

#define BB   128
#define CH   24
#define PIX  1024
#define D    (CH*PIX)
#define MM   5
#define EPSV 1e-5f
#define LAMV 1e-4f

#define RS    35
#define IN1   (24*34*RS)
#define W1SZ  (64*24*9)
#define SMEM1 ((IN1 + W1SZ)*4)

#define IN2C  (32*34*RS)
#define W2SZ  (24*32*9)
#define SMEM2 ((IN2C + W2SZ)*4)

// ---------------- device scratch ----------------
__device__ float g_pre [BB*D];
__device__ float g_xp  [BB*D];
__device__ float g_z   [BB*D];          // current Anderson iterate (single slot)
__device__ float g_F   [MM*BB*D];
__device__ float g_G   [MM*BB*D];       // G_i = F_i - X_i
__device__ float g_t1  [BB*64*PIX];
__device__ float g_H   [BB*MM*MM];      // persistent Gram
__device__ float g_al  [BB*MM];
__device__ float g_s1  [BB*16];
__device__ float g_bmu [CH];
__device__ float g_brs [CH];
__device__ float g_pmu [CH];
__device__ float g_prs [CH];
__device__ float g_pool[BB*CH*16];

// ---------------- block reduce (sum, sumsq) ----------------
__device__ __forceinline__ void block_reduce_2(float& s, float& s2, float* shm) {
    __syncthreads();
    int lane = threadIdx.x & 31, wid = threadIdx.x >> 5;
#pragma unroll
    for (int o = 16; o > 0; o >>= 1) {
        s  += __shfl_down_sync(0xffffffffu, s,  o);
        s2 += __shfl_down_sync(0xffffffffu, s2, o);
    }
    if (lane == 0) { shm[wid] = s; shm[32 + wid] = s2; }
    __syncthreads();
    int nw = (blockDim.x + 31) >> 5;
    if (wid == 0) {
        s  = (lane < nw) ? shm[lane]      : 0.f;
        s2 = (lane < nw) ? shm[32 + lane] : 0.f;
#pragma unroll
        for (int o = 16; o > 0; o >>= 1) {
            s  += __shfl_down_sync(0xffffffffu, s,  o);
            s2 += __shfl_down_sync(0xffffffffu, s2, o);
        }
        if (lane == 0) { shm[0] = s; shm[32] = s2; }
    }
    __syncthreads();
    s = shm[0]; s2 = shm[32];
}

// ---------------- pre conv 3->24 (+bias) ----------------
__global__ void preconv_kernel(const float* __restrict__ x, const float* __restrict__ w,
                               const float* __restrict__ bias, float* __restrict__ out) {
    __shared__ float s[3*34*34];
    int b = blockIdx.x, tid = threadIdx.x;
    for (int i = tid; i < 3*1156; i += 256) {
        int c = i / 1156, rem = i % 1156, r = rem / 34, cx = rem % 34;
        float v = 0.f;
        if (r >= 1 && r <= 32 && cx >= 1 && cx <= 32)
            v = x[((b*3 + c)*32 + (r-1))*32 + (cx-1)];
        s[i] = v;
    }
    __syncthreads();
    int py = tid >> 3, px0 = (tid & 7) << 2;
    for (int oc0 = 0; oc0 < 24; oc0 += 8) {
        float acc[8][4];
#pragma unroll
        for (int j = 0; j < 8; j++) {
            float bv = __ldg(&bias[oc0 + j]);
#pragma unroll
            for (int p = 0; p < 4; p++) acc[j][p] = bv;
        }
        for (int ic = 0; ic < 3; ic++)
#pragma unroll
            for (int ky = 0; ky < 3; ky++) {
                const float* row = &s[ic*1156 + (py + ky)*34 + px0];
                float r0=row[0],r1=row[1],r2=row[2],r3=row[3],r4=row[4],r5=row[5];
#pragma unroll
                for (int j = 0; j < 8; j++) {
                    int oc = oc0 + j;
                    const float* wq = &w[((oc*3 + ic)*3 + ky)*3];
                    float w0=__ldg(wq), w1=__ldg(wq+1), w2=__ldg(wq+2);
                    acc[j][0] += r0*w0 + r1*w1 + r2*w2;
                    acc[j][1] += r1*w0 + r2*w1 + r3*w2;
                    acc[j][2] += r2*w0 + r3*w1 + r4*w2;
                    acc[j][3] += r3*w0 + r4*w1 + r5*w2;
                }
            }
#pragma unroll
        for (int j = 0; j < 8; j++)
#pragma unroll
            for (int p = 0; p < 4; p++)
                out[(b*24 + oc0 + j)*PIX + py*32 + px0 + p] = acc[j][p];
    }
}

// ---------------- batchnorm stats ----------------
__global__ void bn_stats_kernel(const float* __restrict__ in, float* __restrict__ mu,
                                float* __restrict__ rstd, int relu_flag) {
    __shared__ float shm[64];
    int c = blockIdx.x;
    float s = 0.f, s2 = 0.f;
    for (int i = threadIdx.x; i < BB*PIX; i += blockDim.x) {
        int b = i >> 10, p = i & 1023;
        float v = in[(b*CH + c)*PIX + p];
        if (relu_flag) v = fmaxf(v, 0.f);
        s += v; s2 += v*v;
    }
    block_reduce_2(s, s2, shm);
    if (threadIdx.x == 0) {
        float m = s / (float)(BB*PIX);
        float var = s2 / (float)(BB*PIX) - m*m;
        mu[c] = m;
        rstd[c] = rsqrtf(var + EPSV);
    }
}

__global__ void bn_apply_kernel(const float* __restrict__ in, const float* __restrict__ mu,
                                const float* __restrict__ rstd, const float* __restrict__ g,
                                const float* __restrict__ bta, float* __restrict__ out) {
    int idx = blockIdx.x*256 + threadIdx.x;
    if (idx >= BB*D) return;
    int c = (idx >> 10) % CH;
    out[idx] = (in[idx] - mu[c]) * rstd[c] * g[c] + bta[c];
}

// ---------------- conv1: 24->64 3x3 SAME + relu + gn1 stats
//   combine mode: z = sum(alpha_i F_i) computed on the fly, written to zout ----------------
__global__ void __launch_bounds__(512, 1)
conv1_kernel(const float* __restrict__ z, const float* __restrict__ Fb,
             const float* __restrict__ al, float* __restrict__ zout,
             const float* __restrict__ w, float* __restrict__ t1,
             float* __restrict__ s1o) {
    extern __shared__ float s[];
    float* ws = s + IN1;
    __shared__ float gs[8], gq[8];
    int b = blockIdx.x, tid = threadIdx.x;
    const size_t SLOT = (size_t)BB * D;
    if (tid < 8) { gs[tid] = 0.f; gq[tid] = 0.f; }
    for (int i = tid; i < W1SZ; i += 512) ws[i] = w[i];
    if (zout) {
        float a0=al[b*5+0], a1=al[b*5+1], a2=al[b*5+2], a3=al[b*5+3], a4=al[b*5+4];
        for (int i = tid; i < 24*1156; i += 512) {
            int c = i / 1156, rem = i % 1156, r = rem / 34, cx = rem % 34;
            float v = 0.f;
            if (r >= 1 && r <= 32 && cx >= 1 && cx <= 32) {
                size_t off = (size_t)(b*24 + c)*PIX + (r-1)*32 + (cx-1);
                v = a0*Fb[off] + a1*Fb[off + SLOT] + a2*Fb[off + 2*SLOT]
                  + a3*Fb[off + 3*SLOT] + a4*Fb[off + 4*SLOT];
                zout[off] = v;
            }
            s[c*(34*RS) + r*RS + cx] = v;
        }
    } else {
        for (int i = tid; i < 24*1156; i += 512) {
            int c = i / 1156, rem = i % 1156, r = rem / 34, cx = rem % 34;
            float v = 0.f;
            if (r >= 1 && r <= 32 && cx >= 1 && cx <= 32)
                v = z[(size_t)(b*24 + c)*PIX + (r-1)*32 + (cx-1)];
            s[c*(34*RS) + r*RS + cx] = v;
        }
    }
    __syncthreads();
    int ocg = tid >> 7;
    int t = tid & 127;
    int py = t >> 2, px0 = (t & 3) << 3;
    int lane = tid & 31;
#pragma unroll 1
    for (int tile = 0; tile < 2; tile++) {
        int oc0 = tile*32 + ocg*8;
        float acc[8][8];
#pragma unroll
        for (int j = 0; j < 8; j++)
#pragma unroll
            for (int p = 0; p < 8; p++) acc[j][p] = 0.f;
#pragma unroll 1
        for (int ic = 0; ic < 24; ic++)
#pragma unroll
            for (int ky = 0; ky < 3; ky++) {
                const float* row = &s[ic*(34*RS) + (py + ky)*RS + px0];
                float r[10];
#pragma unroll
                for (int p = 0; p < 10; p++) r[p] = row[p];
#pragma unroll
                for (int j = 0; j < 8; j++) {
                    const float* wq = &ws[((oc0 + j)*24 + ic)*9 + ky*3];
                    float w0=wq[0], w1=wq[1], w2=wq[2];
#pragma unroll
                    for (int p = 0; p < 8; p++)
                        acc[j][p] += r[p]*w0 + r[p+1]*w1 + r[p+2]*w2;
                }
            }
        float ss = 0.f, qq = 0.f;
#pragma unroll
        for (int j = 0; j < 8; j++) {
            float v[8];
#pragma unroll
            for (int p = 0; p < 8; p++) {
                v[p] = fmaxf(acc[j][p], 0.f);
                ss += v[p]; qq += v[p]*v[p];
            }
            float4 o0; o0.x=v[0]; o0.y=v[1]; o0.z=v[2]; o0.w=v[3];
            float4 o1; o1.x=v[4]; o1.y=v[5]; o1.z=v[6]; o1.w=v[7];
            float* dst = &t1[(size_t)(b*64 + oc0 + j)*PIX + py*32 + px0];
            *(float4*)dst = o0;
            *(float4*)(dst + 4) = o1;
        }
#pragma unroll
        for (int o = 16; o > 0; o >>= 1) {
            ss += __shfl_down_sync(0xffffffffu, ss, o);
            qq += __shfl_down_sync(0xffffffffu, qq, o);
        }
        if (lane == 0) {
            int grp = oc0 >> 3;
            atomicAdd(&gs[grp], ss);
            atomicAdd(&gq[grp], qq);
        }
    }
    __syncthreads();
    if (tid < 8) {
        float m = gs[tid] * (1.f/8192.f);
        float var = gq[tid] * (1.f/8192.f) - m*m;
        s1o[b*16 + tid*2]     = m;
        s1o[b*16 + tid*2 + 1] = rsqrtf(var + EPSV);
    }
}

// ---------------- conv2f: gn1-affine load, conv 64->24 +xp, gn2 -> +z -> relu -> gn3,
//                  writes F, G=F-z, and Gram row slt of H ----------------
__global__ void __launch_bounds__(512, 1)
conv2f_kernel(const float* __restrict__ t1, const float* __restrict__ w,
              const float* __restrict__ s1, const float* __restrict__ g1g,
              const float* __restrict__ g1b, const float* __restrict__ xp,
              const float* __restrict__ z,
              const float* __restrict__ g2g, const float* __restrict__ b2g,
              const float* __restrict__ g3g, const float* __restrict__ b3g,
              float* __restrict__ Fout, float* __restrict__ Gbuf,
              const float* __restrict__ Gall, int slt, float* __restrict__ Hb) {
    extern __shared__ float s[];
    float* ws = s + IN2C;
    __shared__ float sc[64], bs[64];
    __shared__ float gs2[8], gq2[8], gs3[8], gq3[8];
    __shared__ float st2[16], st3[16];
    __shared__ float hd[MM];
    __shared__ float c2s[CH], c2b[CH], c3s[CH], c3b[CH];
    int b = blockIdx.x, tid = threadIdx.x;
    const size_t SLOT = (size_t)BB * D;
    if (tid < 64) {
        int grp = tid >> 3;
        float m = s1[b*16 + grp*2], rs = s1[b*16 + grp*2 + 1];
        float gam = g1g[tid];
        sc[tid] = rs * gam;
        bs[tid] = g1b[tid] - m * rs * gam;
    }
    if (tid >= 64 && tid < 72) { gs2[tid-64]=0.f; gq2[tid-64]=0.f; gs3[tid-64]=0.f; gq3[tid-64]=0.f; }
    if (tid >= 96 && tid < 96+CH) {
        int c = tid - 96;
        c2s[c] = g2g[c]; c2b[c] = b2g[c];
        c3s[c] = g3g[c]; c3b[c] = b3g[c];
    }
    if (tid >= 128 && tid < 128+MM) hd[tid-128] = 0.f;
    int ocg = tid >> 7;
    int t = tid & 127;
    int py = t >> 2, px0 = (t & 3) << 3;
    int lane = tid & 31;
    float acc[6][8];
#pragma unroll
    for (int j = 0; j < 6; j++)
#pragma unroll
        for (int p = 0; p < 8; p++) acc[j][p] = 0.f;
#pragma unroll 1
    for (int chunk = 0; chunk < 2; chunk++) {
        __syncthreads();
        int icb = chunk * 32;
        for (int i = tid; i < 24*32*9; i += 512) {
            int oc = i / 288, rem = i % 288, ic = rem / 9, k = rem % 9;
            ws[i] = w[(oc*64 + icb + ic)*9 + k];
        }
        for (int i = tid; i < 32*1156; i += 512) {
            int c = i / 1156, rem = i % 1156, r = rem / 34, cx = rem % 34;
            float v = 0.f;
            if (r >= 1 && r <= 32 && cx >= 1 && cx <= 32) {
                int cg = icb + c;
                v = t1[(size_t)(b*64 + cg)*PIX + (r-1)*32 + (cx-1)] * sc[cg] + bs[cg];
            }
            s[c*(34*RS) + r*RS + cx] = v;
        }
        __syncthreads();
#pragma unroll 1
        for (int ic = 0; ic < 32; ic++)
#pragma unroll
            for (int ky = 0; ky < 3; ky++) {
                const float* row = &s[ic*(34*RS) + (py + ky)*RS + px0];
                float r[10];
#pragma unroll
                for (int p = 0; p < 10; p++) r[p] = row[p];
#pragma unroll
                for (int j = 0; j < 6; j++) {
                    const float* wq = &ws[((ocg*6 + j)*32 + ic)*9 + ky*3];
                    float w0=wq[0], w1=wq[1], w2=wq[2];
#pragma unroll
                    for (int p = 0; p < 8; p++)
                        acc[j][p] += r[p]*w0 + r[p+1]*w1 + r[p+2]*w2;
                }
            }
    }
    // ---- epilogue: v = conv + xp ; gn2 stats ----
    float ss[2] = {0.f, 0.f}, qq[2] = {0.f, 0.f};
#pragma unroll
    for (int j = 0; j < 6; j++) {
        size_t idx = (size_t)(b*24 + ocg*6 + j)*PIX + py*32 + px0;
        float4 x0 = *(const float4*)&xp[idx];
        float4 x1 = *(const float4*)&xp[idx + 4];
        acc[j][0]+=x0.x; acc[j][1]+=x0.y; acc[j][2]+=x0.z; acc[j][3]+=x0.w;
        acc[j][4]+=x1.x; acc[j][5]+=x1.y; acc[j][6]+=x1.z; acc[j][7]+=x1.w;
        int u = j / 3;
        float sv = 0.f, qv = 0.f;
#pragma unroll
        for (int p = 0; p < 8; p++) { sv += acc[j][p]; qv += acc[j][p]*acc[j][p]; }
        ss[u] += sv; qq[u] += qv;
    }
#pragma unroll
    for (int o = 16; o > 0; o >>= 1)
#pragma unroll
        for (int u = 0; u < 2; u++) {
            ss[u] += __shfl_down_sync(0xffffffffu, ss[u], o);
            qq[u] += __shfl_down_sync(0xffffffffu, qq[u], o);
        }
    if (lane == 0)
#pragma unroll
        for (int u = 0; u < 2; u++) {
            atomicAdd(&gs2[ocg*2 + u], ss[u]);
            atomicAdd(&gq2[ocg*2 + u], qq[u]);
        }
    __syncthreads();
    if (tid < 8) {
        float m = gs2[tid] * (1.f/3072.f);
        st2[tid*2]   = m;
        st2[tid*2+1] = rsqrtf(gq2[tid] * (1.f/3072.f) - m*m + EPSV);
    }
    __syncthreads();
    // ---- w = relu(z + gn2affine(v)) ; gn3 stats ----
    float s3[2] = {0.f, 0.f}, q3[2] = {0.f, 0.f};
#pragma unroll
    for (int j = 0; j < 6; j++) {
        int c = ocg*6 + j;
        int grp = c / 3;
        float m1 = st2[grp*2], rs1 = st2[grp*2+1];
        float scl = rs1 * c2s[c];
        float off = c2b[c] - m1 * scl;
        size_t idx = (size_t)(b*24 + c)*PIX + py*32 + px0;
        float4 z0 = *(const float4*)&z[idx];
        float4 z1 = *(const float4*)&z[idx + 4];
        float zv[8] = {z0.x,z0.y,z0.z,z0.w,z1.x,z1.y,z1.z,z1.w};
        int u = j / 3;
        float sv = 0.f, qv = 0.f;
#pragma unroll
        for (int p = 0; p < 8; p++) {
            float wv = fmaxf(zv[p] + acc[j][p]*scl + off, 0.f);
            acc[j][p] = wv;
            sv += wv; qv += wv*wv;
        }
        s3[u] += sv; q3[u] += qv;
    }
#pragma unroll
    for (int o = 16; o > 0; o >>= 1)
#pragma unroll
        for (int u = 0; u < 2; u++) {
            s3[u] += __shfl_down_sync(0xffffffffu, s3[u], o);
            q3[u] += __shfl_down_sync(0xffffffffu, q3[u], o);
        }
    if (lane == 0)
#pragma unroll
        for (int u = 0; u < 2; u++) {
            atomicAdd(&gs3[ocg*2 + u], s3[u]);
            atomicAdd(&gq3[ocg*2 + u], q3[u]);
        }
    __syncthreads();
    if (tid < 8) {
        float m = gs3[tid] * (1.f/3072.f);
        st3[tid*2]   = m;
        st3[tid*2+1] = rsqrtf(gq3[tid] * (1.f/3072.f) - m*m + EPSV);
    }
    __syncthreads();
    // ---- F = gn3affine(w); G = F - z; dot row slt ----
    float dot[MM];
#pragma unroll
    for (int i = 0; i < MM; i++) dot[i] = 0.f;
#pragma unroll
    for (int j = 0; j < 6; j++) {
        int c = ocg*6 + j;
        int grp = c / 3;
        float m2 = st3[grp*2], rs2 = st3[grp*2+1];
        float scl = rs2 * c3s[c];
        float off = c3b[c] - m2 * scl;
        size_t idx = (size_t)(b*24 + c)*PIX + py*32 + px0;
        float4 z0 = *(const float4*)&z[idx];
        float4 z1 = *(const float4*)&z[idx + 4];
        float zv[8] = {z0.x,z0.y,z0.z,z0.w,z1.x,z1.y,z1.z,z1.w};
        float fv[8], gv[8];
#pragma unroll
        for (int p = 0; p < 8; p++) {
            fv[p] = acc[j][p]*scl + off;
            gv[p] = fv[p] - zv[p];
        }
        float4 f0; f0.x=fv[0]; f0.y=fv[1]; f0.z=fv[2]; f0.w=fv[3];
        float4 f1; f1.x=fv[4]; f1.y=fv[5]; f1.z=fv[6]; f1.w=fv[7];
        *(float4*)&Fout[idx] = f0; *(float4*)&Fout[idx + 4] = f1;
        float4 g0; g0.x=gv[0]; g0.y=gv[1]; g0.z=gv[2]; g0.w=gv[3];
        float4 g1; g1.x=gv[4]; g1.y=gv[5]; g1.z=gv[6]; g1.w=gv[7];
        *(float4*)&Gbuf[idx] = g0; *(float4*)&Gbuf[idx + 4] = g1;
#pragma unroll
        for (int i = 0; i < MM; i++) {
            if (i == slt) {
#pragma unroll
                for (int p = 0; p < 8; p++) dot[i] += gv[p]*gv[p];
            } else {
                const float* Gi = Gall + (size_t)i * SLOT + idx;
                float4 a0 = *(const float4*)Gi;
                float4 a1 = *(const float4*)(Gi + 4);
                dot[i] += gv[0]*a0.x + gv[1]*a0.y + gv[2]*a0.z + gv[3]*a0.w
                        + gv[4]*a1.x + gv[5]*a1.y + gv[6]*a1.z + gv[7]*a1.w;
            }
        }
    }
#pragma unroll
    for (int o = 16; o > 0; o >>= 1)
#pragma unroll
        for (int i = 0; i < MM; i++)
            dot[i] += __shfl_down_sync(0xffffffffu, dot[i], o);
    if (lane == 0)
#pragma unroll
        for (int i = 0; i < MM; i++) atomicAdd(&hd[i], dot[i]);
    __syncthreads();
    if (tid < MM) {
        float v = hd[tid];
        Hb[b*25 + slt*5 + tid] = v;
        Hb[b*25 + tid*5 + slt] = v;
    }
}

// ---------------- per-batch (n+1)x(n+1) solve ----------------
__global__ void solve_kernel(int n, const float* __restrict__ H, float* __restrict__ alpha) {
    int b = blockIdx.x * blockDim.x + threadIdx.x;
    if (b >= BB) return;
    int m = n + 1;
    float A[6][7];
    for (int i = 0; i < m; i++)
        for (int j = 0; j <= m; j++) A[i][j] = 0.f;
    for (int j = 1; j < m; j++) { A[0][j] = 1.f; A[j][0] = 1.f; }
    for (int i = 0; i < n; i++)
        for (int j = 0; j < n; j++)
            A[i+1][j+1] = H[b*25 + i*5 + j] + ((i == j) ? LAMV : 0.f);
    A[0][m] = 1.f;
    for (int col = 0; col < m; col++) {
        int piv = col; float best = fabsf(A[col][col]);
        for (int r = col + 1; r < m; r++) {
            float v = fabsf(A[r][col]);
            if (v > best) { best = v; piv = r; }
        }
        if (piv != col)
            for (int j = col; j <= m; j++) { float tv = A[col][j]; A[col][j] = A[piv][j]; A[piv][j] = tv; }
        float inv = 1.f / A[col][col];
        for (int r = col + 1; r < m; r++) {
            float f = A[r][col] * inv;
            for (int j = col; j <= m; j++) A[r][j] -= f * A[col][j];
        }
    }
    float xs[6];
    for (int i = m - 1; i >= 0; i--) {
        float v = A[i][m];
        for (int j = i + 1; j < m; j++) v -= A[i][j] * xs[j];
        xs[i] = v / A[i][i];
    }
    for (int i = 0; i < 5; i++) alpha[b*5 + i] = (i < n) ? xs[i + 1] : 0.f;
}

// ---------------- post: relu -> BN apply -> 8x8 avgpool ----------------
__global__ void pool_kernel(const float* __restrict__ z, const float* __restrict__ mu,
                            const float* __restrict__ rstd, const float* __restrict__ g,
                            const float* __restrict__ bta, float* __restrict__ pooled) {
    __shared__ float pl[16];
    int b = blockIdx.x / 24, c = blockIdx.x % 24;
    if (threadIdx.x < 16) pl[threadIdx.x] = 0.f;
    __syncthreads();
    float mc = mu[c], rc = rstd[c], gc = g[c], bc = bta[c];
    for (int i = threadIdx.x; i < 1024; i += 256) {
        int yy = i >> 5, xx = i & 31;
        float v = fmaxf(z[(b*24 + c)*PIX + i], 0.f);
        v = (v - mc) * rc * gc + bc;
        atomicAdd(&pl[(yy >> 3)*4 + (xx >> 3)], v);
    }
    __syncthreads();
    if (threadIdx.x < 16)
        pooled[(b*24 + c)*16 + threadIdx.x] = pl[threadIdx.x] * (1.f/64.f);
}

// ---------------- final FC ----------------
__global__ void fc_kernel(const float* __restrict__ pooled, const float* __restrict__ w,
                          const float* __restrict__ bias, float* __restrict__ out) {
    int b = blockIdx.x;
    int warp = threadIdx.x >> 5, lane = threadIdx.x & 31;
    float acc = 0.f;
    for (int k = lane; k < 384; k += 32)
        acc += pooled[b*384 + k] * w[warp*384 + k];
#pragma unroll
    for (int o = 16; o > 0; o >>= 1) acc += __shfl_down_sync(0xffffffffu, acc, o);
    if (lane == 0) out[b*10 + warp] = acc + bias[warp];
}

// ---------------- host orchestration ----------------
extern "C" void kernel_launch(void* const* d_in, const int* in_sizes, int n_in,
                              void* d_out, int out_size) {
    const float* x     = (const float*)d_in[0];
    const float* pw    = (const float*)d_in[1];
    const float* pbia  = (const float*)d_in[2];
    const float* pbn_g = (const float*)d_in[3];
    const float* pbn_b = (const float*)d_in[4];
    const float* w1    = (const float*)d_in[5];
    const float* g1g   = (const float*)d_in[6];
    const float* g1b   = (const float*)d_in[7];
    const float* w2    = (const float*)d_in[8];
    const float* g2g   = (const float*)d_in[9];
    const float* g2b   = (const float*)d_in[10];
    const float* g3g   = (const float*)d_in[11];
    const float* g3b   = (const float*)d_in[12];
    const float* qbn_g = (const float*)d_in[13];
    const float* qbn_b = (const float*)d_in[14];
    const float* fcw   = (const float*)d_in[15];
    const float* fcb   = (const float*)d_in[16];
    float* out = (float*)d_out;

    static bool attr_done = false;
    if (!attr_done) {
        cudaFuncSetAttribute(conv1_kernel,  cudaFuncAttributeMaxDynamicSharedMemorySize, SMEM1);
        cudaFuncSetAttribute(conv2f_kernel, cudaFuncAttributeMaxDynamicSharedMemorySize, SMEM2);
        attr_done = true;
    }

    float *zb, *Fb, *Gb, *xp, *pre, *t1, *Hb, *al, *s1;
    float *bmu, *brs, *pmu, *prs, *pl;
    cudaGetSymbolAddress((void**)&zb,  g_z);
    cudaGetSymbolAddress((void**)&Fb,  g_F);
    cudaGetSymbolAddress((void**)&Gb,  g_G);
    cudaGetSymbolAddress((void**)&xp,  g_xp);
    cudaGetSymbolAddress((void**)&pre, g_pre);
    cudaGetSymbolAddress((void**)&t1,  g_t1);
    cudaGetSymbolAddress((void**)&Hb,  g_H);
    cudaGetSymbolAddress((void**)&al,  g_al);
    cudaGetSymbolAddress((void**)&s1,  g_s1);
    cudaGetSymbolAddress((void**)&bmu, g_bmu);
    cudaGetSymbolAddress((void**)&brs, g_brs);
    cudaGetSymbolAddress((void**)&pmu, g_pmu);
    cudaGetSymbolAddress((void**)&prs, g_prs);
    cudaGetSymbolAddress((void**)&pl,  g_pool);

    const size_t SLOT = (size_t)BB * D;

    preconv_kernel<<<128, 256>>>(x, pw, pbia, pre);
    bn_stats_kernel<<<24, 512>>>(pre, bmu, brs, 0);
    bn_apply_kernel<<<(BB*D + 255)/256, 256>>>(pre, bmu, brs, pbn_g, pbn_b, xp);

    cudaMemsetAsync(zb, 0, SLOT * sizeof(float));

    auto runf = [&](bool combine, int slt) {
        conv1_kernel<<<128, 512, SMEM1>>>(zb, Fb, al, combine ? zb : nullptr, w1, t1, s1);
        conv2f_kernel<<<128, 512, SMEM2>>>(t1, w2, s1, g1g, g1b, xp, zb,
                                           g2g, g2b, g3g, g3b,
                                           Fb + (size_t)slt*SLOT, Gb + (size_t)slt*SLOT,
                                           Gb, slt, Hb);
    };

    runf(false, 0);                                               // F0 = f(0), X0 = 0
    cudaMemcpyAsync(zb, Fb, SLOT * sizeof(float), cudaMemcpyDeviceToDevice);  // X1 = F0
    runf(false, 1);                                               // F1 = f(F0)

    for (int k = 2; k < 25; k++) {
        int n = (k < 5) ? k : 5;
        solve_kernel<<<1, 128>>>(n, Hb, al);
        runf(true, k % 5);                                        // conv1 builds z = sum(alpha F)
    }

    const float* zf = Fb + 4 * SLOT;   // z = f(z_star) = F[:,4]

    bn_stats_kernel<<<24, 512>>>(zf, pmu, prs, 1);
    pool_kernel<<<128*24, 256>>>(zf, pmu, prs, qbn_g, qbn_b, pl);
    fc_kernel<<<128, 320>>>(pl, fcw, fcb, out);
}

// round 6
// speedup vs baseline: 1.9688x; 1.1621x over previous
#include <cuda_runtime.h>
#include <cuda_bf16.h>
#include <math.h>

#define BB   128
#define CH   24
#define PIX  1024
#define D    (CH*PIX)
#define MM   5
#define EPSV 1e-5f
#define LAMV 1e-4f

#define RS    35
#define IN1   (24*34*RS)
#define W1SZ  (64*24*9)
#define SMEM1 ((IN1 + W1SZ)*4)

#define IN2C  (32*34*RS)
#define W2SZ  (24*32*9)
#define SMEM2 ((IN2C + W2SZ)*4)

// ---------------- device scratch ----------------
__device__ float g_pre [BB*D];
__device__ float g_xp  [BB*D];
__device__ float g_z   [BB*D];
__device__ float g_F   [MM*BB*D];
__device__ float g_G   [MM*BB*D];
__device__ float g_t1  [BB*64*PIX];
__device__ float g_H   [BB*MM*MM];
__device__ float g_al  [BB*MM];
__device__ float g_s1  [BB*16];
__device__ float g_bmu [CH];
__device__ float g_brs [CH];
__device__ float g_pmu [CH];
__device__ float g_prs [CH];
__device__ float g_pool[BB*CH*16];

// ---------------- block reduce (sum, sumsq) ----------------
__device__ __forceinline__ void block_reduce_2(float& s, float& s2, float* shm) {
    __syncthreads();
    int lane = threadIdx.x & 31, wid = threadIdx.x >> 5;
#pragma unroll
    for (int o = 16; o > 0; o >>= 1) {
        s  += __shfl_down_sync(0xffffffffu, s,  o);
        s2 += __shfl_down_sync(0xffffffffu, s2, o);
    }
    if (lane == 0) { shm[wid] = s; shm[32 + wid] = s2; }
    __syncthreads();
    int nw = (blockDim.x + 31) >> 5;
    if (wid == 0) {
        s  = (lane < nw) ? shm[lane]      : 0.f;
        s2 = (lane < nw) ? shm[32 + lane] : 0.f;
#pragma unroll
        for (int o = 16; o > 0; o >>= 1) {
            s  += __shfl_down_sync(0xffffffffu, s,  o);
            s2 += __shfl_down_sync(0xffffffffu, s2, o);
        }
        if (lane == 0) { shm[0] = s; shm[32] = s2; }
    }
    __syncthreads();
    s = shm[0]; s2 = shm[32];
}

// ---------------- pre conv 3->24 (+bias) ----------------
__global__ void preconv_kernel(const float* __restrict__ x, const float* __restrict__ w,
                               const float* __restrict__ bias, float* __restrict__ out) {
    __shared__ float s[3*34*34];
    int b = blockIdx.x, tid = threadIdx.x;
    for (int i = tid; i < 3*1156; i += 256) {
        int c = i / 1156, rem = i % 1156, r = rem / 34, cx = rem % 34;
        float v = 0.f;
        if (r >= 1 && r <= 32 && cx >= 1 && cx <= 32)
            v = x[((b*3 + c)*32 + (r-1))*32 + (cx-1)];
        s[i] = v;
    }
    __syncthreads();
    int py = tid >> 3, px0 = (tid & 7) << 2;
    for (int oc0 = 0; oc0 < 24; oc0 += 8) {
        float acc[8][4];
#pragma unroll
        for (int j = 0; j < 8; j++) {
            float bv = __ldg(&bias[oc0 + j]);
#pragma unroll
            for (int p = 0; p < 4; p++) acc[j][p] = bv;
        }
        for (int ic = 0; ic < 3; ic++)
#pragma unroll
            for (int ky = 0; ky < 3; ky++) {
                const float* row = &s[ic*1156 + (py + ky)*34 + px0];
                float r0=row[0],r1=row[1],r2=row[2],r3=row[3],r4=row[4],r5=row[5];
#pragma unroll
                for (int j = 0; j < 8; j++) {
                    int oc = oc0 + j;
                    const float* wq = &w[((oc*3 + ic)*3 + ky)*3];
                    float w0=__ldg(wq), w1=__ldg(wq+1), w2=__ldg(wq+2);
                    acc[j][0] += r0*w0 + r1*w1 + r2*w2;
                    acc[j][1] += r1*w0 + r2*w1 + r3*w2;
                    acc[j][2] += r2*w0 + r3*w1 + r4*w2;
                    acc[j][3] += r3*w0 + r4*w1 + r5*w2;
                }
            }
#pragma unroll
        for (int j = 0; j < 8; j++)
#pragma unroll
            for (int p = 0; p < 4; p++)
                out[(b*24 + oc0 + j)*PIX + py*32 + px0 + p] = acc[j][p];
    }
}

// ---------------- batchnorm stats ----------------
__global__ void bn_stats_kernel(const float* __restrict__ in, float* __restrict__ mu,
                                float* __restrict__ rstd, int relu_flag) {
    __shared__ float shm[64];
    int c = blockIdx.x;
    float s = 0.f, s2 = 0.f;
    for (int i = threadIdx.x; i < BB*PIX; i += blockDim.x) {
        int b = i >> 10, p = i & 1023;
        float v = in[(b*CH + c)*PIX + p];
        if (relu_flag) v = fmaxf(v, 0.f);
        s += v; s2 += v*v;
    }
    block_reduce_2(s, s2, shm);
    if (threadIdx.x == 0) {
        float m = s / (float)(BB*PIX);
        float var = s2 / (float)(BB*PIX) - m*m;
        mu[c] = m;
        rstd[c] = rsqrtf(var + EPSV);
    }
}

__global__ void bn_apply_kernel(const float* __restrict__ in, const float* __restrict__ mu,
                                const float* __restrict__ rstd, const float* __restrict__ g,
                                const float* __restrict__ bta, float* __restrict__ out) {
    int idx = blockIdx.x*256 + threadIdx.x;
    if (idx >= BB*D) return;
    int c = (idx >> 10) % CH;
    out[idx] = (in[idx] - mu[c]) * rstd[c] * g[c] + bta[c];
}

// ---------------- conv1: 24->64 3x3 SAME + relu + gn1 stats
//   combine mode: z = sum(alpha_i F_i) computed on the fly, written to zout ----------------
__global__ void __launch_bounds__(512, 1)
conv1_kernel(const float* __restrict__ z, const float* __restrict__ Fb,
             const float* __restrict__ al, float* __restrict__ zout,
             const float* __restrict__ w, float* __restrict__ t1,
             float* __restrict__ s1o) {
    extern __shared__ float s[];
    float* ws = s + IN1;
    __shared__ float gs[8], gq[8];
    int b = blockIdx.x, tid = threadIdx.x;
    const size_t SLOT = (size_t)BB * D;
    if (tid < 8) { gs[tid] = 0.f; gq[tid] = 0.f; }
    // zero input region (borders), vector weight copy
    for (int i = tid; i < IN1; i += 512) s[i] = 0.f;
    {
        const float4* w4 = (const float4*)w;
        float4* ws4 = (float4*)ws;
        for (int i = tid; i < W1SZ/4; i += 512) ws4[i] = w4[i];
    }
    __syncthreads();
    if (zout) {
        float a0=al[b*5+0], a1=al[b*5+1], a2=al[b*5+2], a3=al[b*5+3], a4=al[b*5+4];
        for (int task = tid; task < 768; task += 512) {
            int c = task >> 5, gr = task & 31;
            size_t off = (size_t)(b*24 + c)*PIX + gr*32;
            const float4* f0 = (const float4*)(Fb + off);
            const float4* f1 = (const float4*)(Fb + off + SLOT);
            const float4* f2 = (const float4*)(Fb + off + 2*SLOT);
            const float4* f3 = (const float4*)(Fb + off + 3*SLOT);
            const float4* f4 = (const float4*)(Fb + off + 4*SLOT);
            float4* zo = (float4*)(zout + off);
            float* dst = &s[c*(34*RS) + (gr+1)*RS + 1];
#pragma unroll
            for (int q = 0; q < 8; q++) {
                float4 v0=f0[q], v1=f1[q], v2=f2[q], v3=f3[q], v4=f4[q];
                float4 r;
                r.x = a0*v0.x + a1*v1.x + a2*v2.x + a3*v3.x + a4*v4.x;
                r.y = a0*v0.y + a1*v1.y + a2*v2.y + a3*v3.y + a4*v4.y;
                r.z = a0*v0.z + a1*v1.z + a2*v2.z + a3*v3.z + a4*v4.z;
                r.w = a0*v0.w + a1*v1.w + a2*v2.w + a3*v3.w + a4*v4.w;
                zo[q] = r;
                dst[q*4+0]=r.x; dst[q*4+1]=r.y; dst[q*4+2]=r.z; dst[q*4+3]=r.w;
            }
        }
    } else {
        for (int task = tid; task < 768; task += 512) {
            int c = task >> 5, gr = task & 31;
            size_t off = (size_t)(b*24 + c)*PIX + gr*32;
            const float4* zp = (const float4*)(z + off);
            float* dst = &s[c*(34*RS) + (gr+1)*RS + 1];
#pragma unroll
            for (int q = 0; q < 8; q++) {
                float4 v = zp[q];
                dst[q*4+0]=v.x; dst[q*4+1]=v.y; dst[q*4+2]=v.z; dst[q*4+3]=v.w;
            }
        }
    }
    __syncthreads();
    int ocg = tid >> 7;
    int t = tid & 127;
    int py = t >> 2, px0 = (t & 3) << 3;
    int lane = tid & 31;
#pragma unroll 1
    for (int tile = 0; tile < 2; tile++) {
        int oc0 = tile*32 + ocg*8;
        float acc[8][8];
#pragma unroll
        for (int j = 0; j < 8; j++)
#pragma unroll
            for (int p = 0; p < 8; p++) acc[j][p] = 0.f;
#pragma unroll 1
        for (int ic = 0; ic < 24; ic++)
#pragma unroll
            for (int ky = 0; ky < 3; ky++) {
                const float* row = &s[ic*(34*RS) + (py + ky)*RS + px0];
                float r[10];
#pragma unroll
                for (int p = 0; p < 10; p++) r[p] = row[p];
#pragma unroll
                for (int j = 0; j < 8; j++) {
                    const float* wq = &ws[((oc0 + j)*24 + ic)*9 + ky*3];
                    float w0=wq[0], w1=wq[1], w2=wq[2];
#pragma unroll
                    for (int p = 0; p < 8; p++)
                        acc[j][p] += r[p]*w0 + r[p+1]*w1 + r[p+2]*w2;
                }
            }
        float ss = 0.f, qq = 0.f;
#pragma unroll
        for (int j = 0; j < 8; j++) {
            float v[8];
#pragma unroll
            for (int p = 0; p < 8; p++) {
                v[p] = fmaxf(acc[j][p], 0.f);
                ss += v[p]; qq += v[p]*v[p];
            }
            float4 o0; o0.x=v[0]; o0.y=v[1]; o0.z=v[2]; o0.w=v[3];
            float4 o1; o1.x=v[4]; o1.y=v[5]; o1.z=v[6]; o1.w=v[7];
            float* dst = &t1[(size_t)(b*64 + oc0 + j)*PIX + py*32 + px0];
            *(float4*)dst = o0;
            *(float4*)(dst + 4) = o1;
        }
#pragma unroll
        for (int o = 16; o > 0; o >>= 1) {
            ss += __shfl_down_sync(0xffffffffu, ss, o);
            qq += __shfl_down_sync(0xffffffffu, qq, o);
        }
        if (lane == 0) {
            int grp = oc0 >> 3;
            atomicAdd(&gs[grp], ss);
            atomicAdd(&gq[grp], qq);
        }
    }
    __syncthreads();
    if (tid < 8) {
        float m = gs[tid] * (1.f/8192.f);
        float var = gq[tid] * (1.f/8192.f) - m*m;
        s1o[b*16 + tid*2]     = m;
        s1o[b*16 + tid*2 + 1] = rsqrtf(var + EPSV);
    }
}

// ---------------- conv2f: gn1-affine load, conv 64->24 +xp, gn2 -> +z -> relu -> gn3,
//   writes F, G=F-z, Gram row slt of H, and (tid 0) next iteration's alpha ----------------
__global__ void __launch_bounds__(512, 1)
conv2f_kernel(const float* __restrict__ t1, const float* __restrict__ w,
              const float* __restrict__ s1, const float* __restrict__ g1g,
              const float* __restrict__ g1b, const float* __restrict__ xp,
              const float* __restrict__ z,
              const float* __restrict__ g2g, const float* __restrict__ b2g,
              const float* __restrict__ g3g, const float* __restrict__ b3g,
              float* __restrict__ Fout, float* __restrict__ Gbuf,
              const float* __restrict__ Gall, int slt, float* __restrict__ Hb,
              int next_n, float* __restrict__ alpha) {
    extern __shared__ float s[];
    float* ws = s + IN2C;
    __shared__ float sc[64], bs[64];
    __shared__ float gs2[8], gq2[8], gs3[8], gq3[8];
    __shared__ float st2[16], st3[16];
    __shared__ float hd[MM];
    __shared__ float c2s[CH], c2b[CH], c3s[CH], c3b[CH];
    int b = blockIdx.x, tid = threadIdx.x;
    const size_t SLOT = (size_t)BB * D;
    if (tid < 64) {
        int grp = tid >> 3;
        float m = s1[b*16 + grp*2], rs = s1[b*16 + grp*2 + 1];
        float gam = g1g[tid];
        sc[tid] = rs * gam;
        bs[tid] = g1b[tid] - m * rs * gam;
    }
    if (tid >= 64 && tid < 72) { gs2[tid-64]=0.f; gq2[tid-64]=0.f; gs3[tid-64]=0.f; gq3[tid-64]=0.f; }
    if (tid >= 96 && tid < 96+CH) {
        int c = tid - 96;
        c2s[c] = g2g[c]; c2b[c] = b2g[c];
        c3s[c] = g3g[c]; c3b[c] = b3g[c];
    }
    if (tid >= 128 && tid < 128+MM) hd[tid-128] = 0.f;
    // zero input region once (borders persist across chunks)
    for (int i = tid; i < IN2C; i += 512) s[i] = 0.f;
    int ocg = tid >> 7;
    int t = tid & 127;
    int py = t >> 2, px0 = (t & 3) << 3;
    int lane = tid & 31;
    float acc[6][8];
#pragma unroll
    for (int j = 0; j < 6; j++)
#pragma unroll
        for (int p = 0; p < 8; p++) acc[j][p] = 0.f;
#pragma unroll 1
    for (int chunk = 0; chunk < 2; chunk++) {
        __syncthreads();
        int icb = chunk * 32;
        {
            float4* ws4 = (float4*)ws;
            for (int i4 = tid; i4 < 1728; i4 += 512) {
                int oc = i4 / 72, rem = i4 - oc*72;
                ws4[i4] = *(const float4*)(w + oc*576 + icb*9 + rem*4);
            }
        }
        for (int task = tid; task < 1024; task += 512) {
            int c = task >> 5, gr = task & 31;
            int cg = icb + c;
            float scv = sc[cg], bsv = bs[cg];
            const float4* tp = (const float4*)(t1 + (size_t)(b*64 + cg)*PIX + gr*32);
            float* dst = &s[c*(34*RS) + (gr+1)*RS + 1];
#pragma unroll
            for (int q = 0; q < 8; q++) {
                float4 v = tp[q];
                dst[q*4+0] = v.x*scv + bsv;
                dst[q*4+1] = v.y*scv + bsv;
                dst[q*4+2] = v.z*scv + bsv;
                dst[q*4+3] = v.w*scv + bsv;
            }
        }
        __syncthreads();
#pragma unroll 1
        for (int ic = 0; ic < 32; ic++)
#pragma unroll
            for (int ky = 0; ky < 3; ky++) {
                const float* row = &s[ic*(34*RS) + (py + ky)*RS + px0];
                float r[10];
#pragma unroll
                for (int p = 0; p < 10; p++) r[p] = row[p];
#pragma unroll
                for (int j = 0; j < 6; j++) {
                    const float* wq = &ws[((ocg*6 + j)*32 + ic)*9 + ky*3];
                    float w0=wq[0], w1=wq[1], w2=wq[2];
#pragma unroll
                    for (int p = 0; p < 8; p++)
                        acc[j][p] += r[p]*w0 + r[p+1]*w1 + r[p+2]*w2;
                }
            }
    }
    // ---- v = conv + xp ; gn2 stats ----
    float ss[2] = {0.f, 0.f}, qq[2] = {0.f, 0.f};
#pragma unroll
    for (int j = 0; j < 6; j++) {
        size_t idx = (size_t)(b*24 + ocg*6 + j)*PIX + py*32 + px0;
        float4 x0 = *(const float4*)&xp[idx];
        float4 x1 = *(const float4*)&xp[idx + 4];
        acc[j][0]+=x0.x; acc[j][1]+=x0.y; acc[j][2]+=x0.z; acc[j][3]+=x0.w;
        acc[j][4]+=x1.x; acc[j][5]+=x1.y; acc[j][6]+=x1.z; acc[j][7]+=x1.w;
        int u = j / 3;
        float sv = 0.f, qv = 0.f;
#pragma unroll
        for (int p = 0; p < 8; p++) { sv += acc[j][p]; qv += acc[j][p]*acc[j][p]; }
        ss[u] += sv; qq[u] += qv;
    }
#pragma unroll
    for (int o = 16; o > 0; o >>= 1)
#pragma unroll
        for (int u = 0; u < 2; u++) {
            ss[u] += __shfl_down_sync(0xffffffffu, ss[u], o);
            qq[u] += __shfl_down_sync(0xffffffffu, qq[u], o);
        }
    if (lane == 0)
#pragma unroll
        for (int u = 0; u < 2; u++) {
            atomicAdd(&gs2[ocg*2 + u], ss[u]);
            atomicAdd(&gq2[ocg*2 + u], qq[u]);
        }
    __syncthreads();
    if (tid < 8) {
        float m = gs2[tid] * (1.f/3072.f);
        st2[tid*2]   = m;
        st2[tid*2+1] = rsqrtf(gq2[tid] * (1.f/3072.f) - m*m + EPSV);
    }
    __syncthreads();
    // ---- w = relu(z + gn2affine(v)) ; gn3 stats ----
    float s3[2] = {0.f, 0.f}, q3[2] = {0.f, 0.f};
#pragma unroll
    for (int j = 0; j < 6; j++) {
        int c = ocg*6 + j;
        int grp = c / 3;
        float m1 = st2[grp*2], rs1 = st2[grp*2+1];
        float scl = rs1 * c2s[c];
        float off = c2b[c] - m1 * scl;
        size_t idx = (size_t)(b*24 + c)*PIX + py*32 + px0;
        float4 z0 = *(const float4*)&z[idx];
        float4 z1 = *(const float4*)&z[idx + 4];
        float zv[8] = {z0.x,z0.y,z0.z,z0.w,z1.x,z1.y,z1.z,z1.w};
        int u = j / 3;
        float sv = 0.f, qv = 0.f;
#pragma unroll
        for (int p = 0; p < 8; p++) {
            float wv = fmaxf(zv[p] + acc[j][p]*scl + off, 0.f);
            acc[j][p] = wv;
            sv += wv; qv += wv*wv;
        }
        s3[u] += sv; q3[u] += qv;
    }
#pragma unroll
    for (int o = 16; o > 0; o >>= 1)
#pragma unroll
        for (int u = 0; u < 2; u++) {
            s3[u] += __shfl_down_sync(0xffffffffu, s3[u], o);
            q3[u] += __shfl_down_sync(0xffffffffu, q3[u], o);
        }
    if (lane == 0)
#pragma unroll
        for (int u = 0; u < 2; u++) {
            atomicAdd(&gs3[ocg*2 + u], s3[u]);
            atomicAdd(&gq3[ocg*2 + u], q3[u]);
        }
    __syncthreads();
    if (tid < 8) {
        float m = gs3[tid] * (1.f/3072.f);
        st3[tid*2]   = m;
        st3[tid*2+1] = rsqrtf(gq3[tid] * (1.f/3072.f) - m*m + EPSV);
    }
    __syncthreads();
    // ---- F = gn3affine(w); G = F - z; dot row slt ----
    float dot[MM];
#pragma unroll
    for (int i = 0; i < MM; i++) dot[i] = 0.f;
#pragma unroll
    for (int j = 0; j < 6; j++) {
        int c = ocg*6 + j;
        int grp = c / 3;
        float m2 = st3[grp*2], rs2 = st3[grp*2+1];
        float scl = rs2 * c3s[c];
        float off = c3b[c] - m2 * scl;
        size_t idx = (size_t)(b*24 + c)*PIX + py*32 + px0;
        float4 z0 = *(const float4*)&z[idx];
        float4 z1 = *(const float4*)&z[idx + 4];
        float zv[8] = {z0.x,z0.y,z0.z,z0.w,z1.x,z1.y,z1.z,z1.w};
        float fv[8], gv[8];
#pragma unroll
        for (int p = 0; p < 8; p++) {
            fv[p] = acc[j][p]*scl + off;
            gv[p] = fv[p] - zv[p];
        }
        float4 f0; f0.x=fv[0]; f0.y=fv[1]; f0.z=fv[2]; f0.w=fv[3];
        float4 f1; f1.x=fv[4]; f1.y=fv[5]; f1.z=fv[6]; f1.w=fv[7];
        *(float4*)&Fout[idx] = f0; *(float4*)&Fout[idx + 4] = f1;
        float4 g0; g0.x=gv[0]; g0.y=gv[1]; g0.z=gv[2]; g0.w=gv[3];
        float4 g1; g1.x=gv[4]; g1.y=gv[5]; g1.z=gv[6]; g1.w=gv[7];
        *(float4*)&Gbuf[idx] = g0; *(float4*)&Gbuf[idx + 4] = g1;
#pragma unroll
        for (int i = 0; i < MM; i++) {
            if (i == slt) {
#pragma unroll
                for (int p = 0; p < 8; p++) dot[i] += gv[p]*gv[p];
            } else {
                const float* Gi = Gall + (size_t)i * SLOT + idx;
                float4 a0 = *(const float4*)Gi;
                float4 a1 = *(const float4*)(Gi + 4);
                dot[i] += gv[0]*a0.x + gv[1]*a0.y + gv[2]*a0.z + gv[3]*a0.w
                        + gv[4]*a1.x + gv[5]*a1.y + gv[6]*a1.z + gv[7]*a1.w;
            }
        }
    }
#pragma unroll
    for (int o = 16; o > 0; o >>= 1)
#pragma unroll
        for (int i = 0; i < MM; i++)
            dot[i] += __shfl_down_sync(0xffffffffu, dot[i], o);
    if (lane == 0)
#pragma unroll
        for (int i = 0; i < MM; i++) atomicAdd(&hd[i], dot[i]);
    __syncthreads();
    if (tid < MM) {
        float v = hd[tid];
        Hb[b*25 + slt*5 + tid] = v;
        Hb[b*25 + tid*5 + slt] = v;
    }
    __syncthreads();
    // ---- fused solve for next iteration's alpha (thread 0 per block/image) ----
    if (next_n > 0 && tid == 0) {
        int n = next_n, m = n + 1;
        float A[6][7];
        for (int i = 0; i < m; i++)
            for (int j = 0; j <= m; j++) A[i][j] = 0.f;
        for (int j = 1; j < m; j++) { A[0][j] = 1.f; A[j][0] = 1.f; }
        for (int i = 0; i < n; i++)
            for (int j = 0; j < n; j++) {
                float hij = (i == slt) ? hd[j] : ((j == slt) ? hd[i] : Hb[b*25 + i*5 + j]);
                A[i+1][j+1] = hij + ((i == j) ? LAMV : 0.f);
            }
        A[0][m] = 1.f;
        for (int col = 0; col < m; col++) {
            int piv = col; float best = fabsf(A[col][col]);
            for (int r = col + 1; r < m; r++) {
                float v = fabsf(A[r][col]);
                if (v > best) { best = v; piv = r; }
            }
            if (piv != col)
                for (int j = col; j <= m; j++) { float tv = A[col][j]; A[col][j] = A[piv][j]; A[piv][j] = tv; }
            float inv = 1.f / A[col][col];
            for (int r = col + 1; r < m; r++) {
                float f = A[r][col] * inv;
                for (int j = col; j <= m; j++) A[r][j] -= f * A[col][j];
            }
        }
        float xs[6];
        for (int i = m - 1; i >= 0; i--) {
            float v = A[i][m];
            for (int j = i + 1; j < m; j++) v -= A[i][j] * xs[j];
            xs[i] = v / A[i][i];
        }
        for (int i = 0; i < 5; i++) alpha[b*5 + i] = (i < n) ? xs[i + 1] : 0.f;
    }
}

// ---------------- post: relu -> BN apply -> 8x8 avgpool ----------------
__global__ void pool_kernel(const float* __restrict__ z, const float* __restrict__ mu,
                            const float* __restrict__ rstd, const float* __restrict__ g,
                            const float* __restrict__ bta, float* __restrict__ pooled) {
    __shared__ float pl[16];
    int b = blockIdx.x / 24, c = blockIdx.x % 24;
    if (threadIdx.x < 16) pl[threadIdx.x] = 0.f;
    __syncthreads();
    float mc = mu[c], rc = rstd[c], gc = g[c], bc = bta[c];
    for (int i = threadIdx.x; i < 1024; i += 256) {
        int yy = i >> 5, xx = i & 31;
        float v = fmaxf(z[(b*24 + c)*PIX + i], 0.f);
        v = (v - mc) * rc * gc + bc;
        atomicAdd(&pl[(yy >> 3)*4 + (xx >> 3)], v);
    }
    __syncthreads();
    if (threadIdx.x < 16)
        pooled[(b*24 + c)*16 + threadIdx.x] = pl[threadIdx.x] * (1.f/64.f);
}

// ---------------- final FC ----------------
__global__ void fc_kernel(const float* __restrict__ pooled, const float* __restrict__ w,
                          const float* __restrict__ bias, float* __restrict__ out) {
    int b = blockIdx.x;
    int warp = threadIdx.x >> 5, lane = threadIdx.x & 31;
    float acc = 0.f;
    for (int k = lane; k < 384; k += 32)
        acc += pooled[b*384 + k] * w[warp*384 + k];
#pragma unroll
    for (int o = 16; o > 0; o >>= 1) acc += __shfl_down_sync(0xffffffffu, acc, o);
    if (lane == 0) out[b*10 + warp] = acc + bias[warp];
}

// ---------------- host orchestration ----------------
extern "C" void kernel_launch(void* const* d_in, const int* in_sizes, int n_in,
                              void* d_out, int out_size) {
    const float* x     = (const float*)d_in[0];
    const float* pw    = (const float*)d_in[1];
    const float* pbia  = (const float*)d_in[2];
    const float* pbn_g = (const float*)d_in[3];
    const float* pbn_b = (const float*)d_in[4];
    const float* w1    = (const float*)d_in[5];
    const float* g1g   = (const float*)d_in[6];
    const float* g1b   = (const float*)d_in[7];
    const float* w2    = (const float*)d_in[8];
    const float* g2g   = (const float*)d_in[9];
    const float* g2b   = (const float*)d_in[10];
    const float* g3g   = (const float*)d_in[11];
    const float* g3b   = (const float*)d_in[12];
    const float* qbn_g = (const float*)d_in[13];
    const float* qbn_b = (const float*)d_in[14];
    const float* fcw   = (const float*)d_in[15];
    const float* fcb   = (const float*)d_in[16];
    float* out = (float*)d_out;

    static bool attr_done = false;
    if (!attr_done) {
        cudaFuncSetAttribute(conv1_kernel,  cudaFuncAttributeMaxDynamicSharedMemorySize, SMEM1);
        cudaFuncSetAttribute(conv2f_kernel, cudaFuncAttributeMaxDynamicSharedMemorySize, SMEM2);
        attr_done = true;
    }

    float *zb, *Fb, *Gb, *xp, *pre, *t1, *Hb, *al, *s1;
    float *bmu, *brs, *pmu, *prs, *pl;
    cudaGetSymbolAddress((void**)&zb,  g_z);
    cudaGetSymbolAddress((void**)&Fb,  g_F);
    cudaGetSymbolAddress((void**)&Gb,  g_G);
    cudaGetSymbolAddress((void**)&xp,  g_xp);
    cudaGetSymbolAddress((void**)&pre, g_pre);
    cudaGetSymbolAddress((void**)&t1,  g_t1);
    cudaGetSymbolAddress((void**)&Hb,  g_H);
    cudaGetSymbolAddress((void**)&al,  g_al);
    cudaGetSymbolAddress((void**)&s1,  g_s1);
    cudaGetSymbolAddress((void**)&bmu, g_bmu);
    cudaGetSymbolAddress((void**)&brs, g_brs);
    cudaGetSymbolAddress((void**)&pmu, g_pmu);
    cudaGetSymbolAddress((void**)&prs, g_prs);
    cudaGetSymbolAddress((void**)&pl,  g_pool);

    const size_t SLOT = (size_t)BB * D;

    preconv_kernel<<<128, 256>>>(x, pw, pbia, pre);
    bn_stats_kernel<<<24, 512>>>(pre, bmu, brs, 0);
    bn_apply_kernel<<<(BB*D + 255)/256, 256>>>(pre, bmu, brs, pbn_g, pbn_b, xp);

    cudaMemsetAsync(zb, 0, SLOT * sizeof(float));

    auto runf = [&](bool combine, int slt, int next_n) {
        conv1_kernel<<<128, 512, SMEM1>>>(zb, Fb, al, combine ? zb : nullptr, w1, t1, s1);
        conv2f_kernel<<<128, 512, SMEM2>>>(t1, w2, s1, g1g, g1b, xp, zb,
                                           g2g, g2b, g3g, g3b,
                                           Fb + (size_t)slt*SLOT, Gb + (size_t)slt*SLOT,
                                           Gb, slt, Hb, next_n, al);
    };

    runf(false, 0, 0);                                            // F0 = f(0)
    cudaMemcpyAsync(zb, Fb, SLOT * sizeof(float), cudaMemcpyDeviceToDevice);  // X1 = F0
    runf(false, 1, 2);                                            // F1 = f(F0); alpha for k=2

    for (int k = 2; k < 25; k++) {
        int nn = (k + 1 < 5) ? (k + 1) : 5;                       // n for NEXT iteration
        runf(true, k % 5, (k < 24) ? nn : 0);
    }

    const float* zf = Fb + 4 * SLOT;   // z = f(z_star) = F[:,4]

    bn_stats_kernel<<<24, 512>>>(zf, pmu, prs, 1);
    pool_kernel<<<128*24, 256>>>(zf, pmu, prs, qbn_g, qbn_b, pl);
    fc_kernel<<<128, 320>>>(pl, fcw, fcb, out);
}